// round 4
// baseline (speedup 1.0000x reference)
#include <cuda_runtime.h>
#include <cuda_bf16.h>
#include <cstdint>
#include <cstddef>

#define DINL __device__ __forceinline__

// ---------------- problem constants ----------------
namespace {
constexpr int Bn = 16, Sn = 2048, Dn = 1024, On = 1024;
constexpr int Mtot = Bn * Sn;           // 32768 rows
constexpr int Ktot = 2 * Dn;            // 2048 (hidden | enc concat)
constexpr int M_TILE = 128, N_TILE = 128, K_TILE = 32;
constexpr int KT  = Ktot / K_TILE;      // 64 k-iterations
constexpr int NCH = On / N_TILE;        // 8 n-chunks
constexpr int MT  = Mtot / M_TILE;      // 256 m-tiles
constexpr int THREADS = 256;            // 8 warps: 2 (M) x 4 (N)

// smem: padded rows -> conflict-free ldmatrix & cp.async stores
constexpr int ROW_PAD = 40;                       // halves per 32-half row
constexpr int ARR_BYTES = 128 * ROW_PAD * 2;      // 10240 B per operand array
constexpr int A_HI = 0, A_LO = ARR_BYTES, B_HI = 2 * ARR_BYTES, B_LO = 3 * ARR_BYTES;
constexpr int STAGE_BYTES = 4 * ARR_BYTES;        // 40960 B
constexpr int STAGES = 3;
constexpr int SMEM_TOTAL = STAGES * STAGE_BYTES;  // 122880 B
}

// ---------------- scratch (device globals; no allocs allowed) ----------------
__device__ __nv_bfloat16 g_Ahi[(size_t)Mtot * Ktot];   // 128 MB
__device__ __nv_bfloat16 g_Alo[(size_t)Mtot * Ktot];   // 128 MB
__device__ __nv_bfloat16 g_Bhi[(size_t)On * Ktot];     // 4 MB
__device__ __nv_bfloat16 g_Blo[(size_t)On * Ktot];     // 4 MB
__device__ float g_cb[Bn * On];                        // c_t @ W2^T + bias
__device__ float g_part[NCH][Mtot];                    // per-n-chunk logit partials

// ---------------- PTX helpers (all base-sm_80+ features) ----------------
DINL uint32_t smem_u32(const void* p) {
    uint32_t a;
    asm("{ .reg .u64 t; cvta.to.shared.u64 t, %1; cvt.u32.u64 %0, t; }" : "=r"(a) : "l"(p));
    return a;
}
DINL void cp_async16(uint32_t s, const void* g) {
    asm volatile("cp.async.cg.shared.global [%0], [%1], 16;" :: "r"(s), "l"(g));
}
DINL void cp_commit() { asm volatile("cp.async.commit_group;" ::: "memory"); }
template <int N> DINL void cp_wait() { asm volatile("cp.async.wait_group %0;" :: "n"(N) : "memory"); }

DINL void ldsm_x4(uint32_t* r, uint32_t addr) {
    asm volatile("ldmatrix.sync.aligned.m8n8.x4.shared.b16 {%0,%1,%2,%3}, [%4];"
                 : "=r"(r[0]), "=r"(r[1]), "=r"(r[2]), "=r"(r[3]) : "r"(addr));
}
DINL void mma_bf16(float* c, const uint32_t* a, const uint32_t* b) {
    asm volatile(
        "mma.sync.aligned.m16n8k16.row.col.f32.bf16.bf16.f32 "
        "{%0,%1,%2,%3}, {%4,%5,%6,%7}, {%8,%9}, {%0,%1,%2,%3};"
        : "+f"(c[0]), "+f"(c[1]), "+f"(c[2]), "+f"(c[3])
        : "r"(a[0]), "r"(a[1]), "r"(a[2]), "r"(a[3]), "r"(b[0]), "r"(b[1]));
}

// ---------------- fp32 -> bf16 hi/lo split ----------------
DINL void split_store(float4 x, __nv_bfloat16* hi, __nv_bfloat16* lo) {
    float xs[4] = {x.x, x.y, x.z, x.w};
    __nv_bfloat16 h[4], l[4];
#pragma unroll
    for (int i = 0; i < 4; ++i) {
        h[i] = __float2bfloat16(xs[i]);
        l[i] = __float2bfloat16(xs[i] - __bfloat162float(h[i]));
    }
    *reinterpret_cast<uint2*>(hi) = *reinterpret_cast<const uint2*>(h);
    *reinterpret_cast<uint2*>(lo) = *reinterpret_cast<const uint2*>(l);
}

// A = [hidden | enc] as [Mtot x Ktot] hi/lo bf16
__global__ void __launch_bounds__(256) k_convA(const float* __restrict__ hid,
                                               const float* __restrict__ enc) {
    size_t i = (size_t)blockIdx.x * blockDim.x + threadIdx.x;
    constexpr size_t TOT = (size_t)Mtot * Dn / 4;
    if (i >= TOT) return;
    size_t row = (i * 4) / Dn;
    size_t col = (i * 4) % Dn;
    float4 h = reinterpret_cast<const float4*>(hid)[i];
    float4 e = reinterpret_cast<const float4*>(enc)[i];
    size_t o = row * Ktot + col;
    split_store(h, g_Ahi + o, g_Alo + o);
    split_store(e, g_Ahi + o + Dn, g_Alo + o + Dn);
}

// Bcat[o][k] = k<1024 ? W[o][k] : W[o][2048 + (k-1024)]
__global__ void __launch_bounds__(256) k_convB(const float* __restrict__ W) {
    size_t i = (size_t)blockIdx.x * blockDim.x + threadIdx.x;
    constexpr size_t TOT = (size_t)On * Ktot / 4;
    if (i >= TOT) return;
    size_t o = (i * 4) / Ktot;
    size_t k = (i * 4) % Ktot;
    size_t src = o * (size_t)(3 * Dn) + (k < (size_t)Dn ? k : k + Dn);
    float4 w = *reinterpret_cast<const float4*>(W + src);
    split_store(w, g_Bhi + o * Ktot + k, g_Blo + o * Ktot + k);
}

// cb[b][o] = c_t[b] . W[o][1024:2048] + bias[o]   (one warp per output, fp32 exact)
__global__ void __launch_bounds__(256) k_cb(const float* __restrict__ ct,
                                            const float* __restrict__ W,
                                            const float* __restrict__ bias) {
    int gw = blockIdx.x * 8 + (threadIdx.x >> 5);
    int lane = threadIdx.x & 31;
    int b = gw >> 10;
    int o = gw & 1023;
    const float* c = ct + (size_t)b * Dn;
    const float* w = W + (size_t)o * (3 * Dn) + Dn;
    float s = 0.f;
    for (int k = lane; k < Dn; k += 32) s += c[k] * w[k];
#pragma unroll
    for (int off = 16; off; off >>= 1) s += __shfl_xor_sync(0xFFFFFFFFu, s, off);
    if (lane == 0) g_cb[b * On + o] = s + bias[o];
}

// ---------------- fused split-bf16 GEMM (mma.sync) + relu + dot(v) ----------------
DINL void load_stage(uint32_t stg, const __nv_bfloat16* Ah, const __nv_bfloat16* Al,
                     const __nv_bfloat16* Bh, const __nv_bfloat16* Bl, int kb, int tid) {
    // each operand: 128 rows x 4 chunks of 16B; 512 chunks / 256 threads = 2 iters
#pragma unroll
    for (int it = 0; it < 2; ++it) {
        int c = tid + it * THREADS;
        int row = c & 127, kc = c >> 7;                       // kc in 0..3
        uint32_t so = (uint32_t)(row * (ROW_PAD * 2) + kc * 16);
        size_t go = (size_t)row * Ktot + kb + kc * 8;
        cp_async16(stg + A_HI + so, Ah + go);
        cp_async16(stg + A_LO + so, Al + go);
        cp_async16(stg + B_HI + so, Bh + go);
        cp_async16(stg + B_LO + so, Bl + go);
    }
}

__global__ void __launch_bounds__(THREADS, 1) k_gemm(const float* __restrict__ v) {
    extern __shared__ char smem[];
    const uint32_t sb = smem_u32(smem);
    const int tid  = threadIdx.x;
    const int lane = tid & 31, wid = tid >> 5;
    const int wm = wid >> 2, wn = wid & 3;        // 2 x 4 warp grid, warp tile 64x32
    const int nch = blockIdx.x;                   // fast-varying: 8 CTAs share A via L2
    const int m_base = blockIdx.y * M_TILE;
    const int n_base = nch * N_TILE;
    const int bidx = m_base / Sn;                 // tile sits in one batch (128 | 2048)

    const __nv_bfloat16* Ah = g_Ahi + (size_t)m_base * Ktot;
    const __nv_bfloat16* Al = g_Alo + (size_t)m_base * Ktot;
    const __nv_bfloat16* Bh = g_Bhi + (size_t)n_base * Ktot;
    const __nv_bfloat16* Bl = g_Blo + (size_t)n_base * Ktot;

    // ldmatrix per-lane smem offsets (bytes within a stage array)
    const int r_in = lane & 7, grp = lane >> 3;
    uint32_t a_off[4], b_off[2];
#pragma unroll
    for (int mt = 0; mt < 4; ++mt) {
        int row = wm * 64 + mt * 16 + r_in + (grp & 1) * 8;   // groups 0/2: rows, 1/3: rows+8
        a_off[mt] = (uint32_t)(row * (ROW_PAD * 2) + ((grp >> 1) * 8) * 2);  // groups 2,3: k+8
    }
#pragma unroll
    for (int i = 0; i < 2; ++i) {
        int row = wn * 32 + i * 16 + r_in + (grp >> 1) * 8;   // groups 0/1: n, 2/3: n+8
        b_off[i] = (uint32_t)(row * (ROW_PAD * 2) + ((grp & 1) * 8) * 2);    // groups 1,3: k+8
    }

    float acc[4][4][4];
#pragma unroll
    for (int a = 0; a < 4; ++a)
#pragma unroll
        for (int b = 0; b < 4; ++b)
#pragma unroll
            for (int c = 0; c < 4; ++c) acc[a][b][c] = 0.f;

    load_stage(sb, Ah, Al, Bh, Bl, 0, tid);                       cp_commit();
    load_stage(sb + STAGE_BYTES, Ah, Al, Bh, Bl, K_TILE, tid);    cp_commit();

#pragma unroll 1
    for (int kt = 0; kt < KT; ++kt) {
        if (kt == KT - 1) cp_wait<0>(); else cp_wait<1>();
        __syncthreads();
        if (kt + 2 < KT) {
            load_stage(sb + (uint32_t)((kt + 2) % STAGES) * STAGE_BYTES,
                       Ah, Al, Bh, Bl, (kt + 2) * K_TILE, tid);
            cp_commit();
        }
        const uint32_t stg = sb + (uint32_t)(kt % STAGES) * STAGE_BYTES;
#pragma unroll
        for (int k16 = 0; k16 < 2; ++k16) {
            uint32_t ah[4][4], al[4][4], bh[2][4], bl[2][4];
#pragma unroll
            for (int mt = 0; mt < 4; ++mt) {
                ldsm_x4(ah[mt], stg + A_HI + a_off[mt] + k16 * 32);
                ldsm_x4(al[mt], stg + A_LO + a_off[mt] + k16 * 32);
            }
#pragma unroll
            for (int i = 0; i < 2; ++i) {
                ldsm_x4(bh[i], stg + B_HI + b_off[i] + k16 * 32);
                ldsm_x4(bl[i], stg + B_LO + b_off[i] + k16 * 32);
            }
#pragma unroll
            for (int mt = 0; mt < 4; ++mt)
#pragma unroll
                for (int nt = 0; nt < 4; ++nt) {
                    const uint32_t* bhf = &bh[nt >> 1][(nt & 1) * 2];
                    const uint32_t* blf = &bl[nt >> 1][(nt & 1) * 2];
                    mma_bf16(acc[mt][nt], ah[mt], bhf);   // hi*hi
                    mma_bf16(acc[mt][nt], ah[mt], blf);   // hi*lo
                    mma_bf16(acc[mt][nt], al[mt], bhf);   // lo*hi
                }
        }
    }

    // ---- fused epilogue: partial[row] = sum_n relu(acc + cb[n]) * v[n] ----
    __syncthreads();                               // stages dead; reuse smem
    float* red = reinterpret_cast<float*>(smem);   // [128 rows][4 wn]
    const float* cbp = g_cb + bidx * On + n_base;
    const float* vp  = v + n_base;
    float cbv[4][2], vv[4][2];
#pragma unroll
    for (int nt = 0; nt < 4; ++nt)
#pragma unroll
        for (int j = 0; j < 2; ++j) {
            int n = wn * 32 + nt * 8 + 2 * (lane & 3) + j;
            cbv[nt][j] = cbp[n];
            vv[nt][j]  = vp[n];
        }
#pragma unroll
    for (int mt = 0; mt < 4; ++mt)
#pragma unroll
        for (int h = 0; h < 2; ++h) {
            float s = 0.f;
#pragma unroll
            for (int nt = 0; nt < 4; ++nt)
#pragma unroll
                for (int j = 0; j < 2; ++j) {
                    float e = acc[mt][nt][2 * h + j] + cbv[nt][j];
                    s += fmaxf(e, 0.f) * vv[nt][j];
                }
            s += __shfl_xor_sync(0xFFFFFFFFu, s, 1);
            s += __shfl_xor_sync(0xFFFFFFFFu, s, 2);
            if ((lane & 3) == 0) {
                int row = wm * 64 + mt * 16 + (lane >> 2) + 8 * h;
                red[row * 4 + wn] = s;
            }
        }
    __syncthreads();
    if (tid < 128) {
        float sum = red[tid * 4] + red[tid * 4 + 1] + red[tid * 4 + 2] + red[tid * 4 + 3];
        g_part[nch][m_base + tid] = sum;
    }
}

// ---------------- softmax over S per batch ----------------
__global__ void __launch_bounds__(1024) k_softmax(float* __restrict__ out) {
    __shared__ float red[32];
    const int b = blockIdx.x;
    const int t = threadIdx.x;
    const int i0 = b * Sn + t;
    const int i1 = i0 + 1024;
    float l0 = 0.f, l1 = 0.f;
#pragma unroll
    for (int c = 0; c < NCH; ++c) { l0 += g_part[c][i0]; l1 += g_part[c][i1]; }

    float m = fmaxf(l0, l1);
#pragma unroll
    for (int off = 16; off; off >>= 1) m = fmaxf(m, __shfl_xor_sync(0xFFFFFFFFu, m, off));
    if ((t & 31) == 0) red[t >> 5] = m;
    __syncthreads();
    if (t < 32) {
        float x = red[t];
#pragma unroll
        for (int off = 16; off; off >>= 1) x = fmaxf(x, __shfl_xor_sync(0xFFFFFFFFu, x, off));
        if (t == 0) red[0] = x;
    }
    __syncthreads();
    const float M = red[0];
    __syncthreads();

    float e0 = expf(l0 - M), e1 = expf(l1 - M);
    float s = e0 + e1;
#pragma unroll
    for (int off = 16; off; off >>= 1) s += __shfl_xor_sync(0xFFFFFFFFu, s, off);
    if ((t & 31) == 0) red[t >> 5] = s;
    __syncthreads();
    if (t < 32) {
        float x = red[t];
#pragma unroll
        for (int off = 16; off; off >>= 1) x += __shfl_xor_sync(0xFFFFFFFFu, x, off);
        if (t == 0) red[0] = x;
    }
    __syncthreads();
    const float inv = 1.0f / red[0];
    out[i0] = e0 * inv;
    out[i1] = e1 * inv;
}

// ---------------- launch ----------------
extern "C" void kernel_launch(void* const* d_in, const int* in_sizes, int n_in,
                              void* d_out, int out_size) {
    const float* hid  = (const float*)d_in[0];   // [16,2048,1024]
    const float* enc  = (const float*)d_in[1];   // [16,2048,1024]
    const float* ct   = (const float*)d_in[2];   // [16,1024]
    const float* W    = (const float*)d_in[3];   // [1024,3072]
    const float* bias = (const float*)d_in[4];   // [1024]
    const float* v    = (const float*)d_in[5];   // [1024]
    float* out = (float*)d_out;                  // [16,2048]

    cudaFuncSetAttribute(k_gemm, cudaFuncAttributeMaxDynamicSharedMemorySize, SMEM_TOTAL);

    k_convA<<<(unsigned)((size_t)Mtot * Dn / 4 / 256), 256>>>(hid, enc);
    k_convB<<<(unsigned)((size_t)On * Ktot / 4 / 256), 256>>>(W);
    k_cb<<<Bn * On / 8, 256>>>(ct, W, bias);
    dim3 grid(NCH, MT);
    k_gemm<<<grid, THREADS, SMEM_TOTAL>>>(v);
    k_softmax<<<Bn, 1024>>>(out);
}

// round 7
// speedup vs baseline: 1.2304x; 1.2304x over previous
#include <cuda_runtime.h>
#include <cuda_bf16.h>
#include <cstdint>
#include <cstddef>

#define DINL __device__ __forceinline__

// ---------------- problem constants ----------------
namespace {
constexpr int Bn = 16, Sn = 2048, Dn = 1024, On = 1024;
constexpr int Mtot = Bn * Sn;           // 32768 rows
constexpr int Ktot = 2 * Dn;            // 2048 (hidden | enc concat)
constexpr int M_TILE = 256, N_TILE = 128, K_TILE = 32;
constexpr int KT  = Ktot / K_TILE;      // 64 k-iterations
constexpr int NCH = On / N_TILE;        // 8 n-chunks
constexpr int MT  = Mtot / M_TILE;      // 128 m-tiles
constexpr int THREADS = 512;            // 16 warps: 4 (M) x 4 (N), warp tile 64x32

// smem: padded rows -> conflict-free ldmatrix & cp.async stores
constexpr int ROW_PAD = 40;                         // halves per 32-half row (80 B)
constexpr int A_ARR = M_TILE * ROW_PAD * 2;         // 20480 B per A operand array
constexpr int B_ARR = N_TILE * ROW_PAD * 2;         // 10240 B per B operand array
constexpr int A_HI = 0, A_LO = A_ARR;
constexpr int B_HI = 2 * A_ARR, B_LO = 2 * A_ARR + B_ARR;
constexpr int STAGE_BYTES = 2 * A_ARR + 2 * B_ARR;  // 61440 B
constexpr int STAGES = 3;
constexpr int SMEM_TOTAL = STAGES * STAGE_BYTES;    // 184320 B (fits 227KB)
}

// ---------------- scratch (device globals; no allocs allowed) ----------------
__device__ __nv_bfloat16 g_Ahi[(size_t)Mtot * Ktot];   // 128 MB
__device__ __nv_bfloat16 g_Alo[(size_t)Mtot * Ktot];   // 128 MB
__device__ __nv_bfloat16 g_Bhi[(size_t)On * Ktot];     // 4 MB
__device__ __nv_bfloat16 g_Blo[(size_t)On * Ktot];     // 4 MB
__device__ float g_cb[Bn * On];                        // c_t @ W2^T + bias
__device__ float g_part[NCH][Mtot];                    // per-n-chunk logit partials

// ---------------- PTX helpers (base sm_80+ only; no tcgen05 on sm_103 base) ----
DINL uint32_t smem_u32(const void* p) {
    uint32_t a;
    asm("{ .reg .u64 t; cvta.to.shared.u64 t, %1; cvt.u32.u64 %0, t; }" : "=r"(a) : "l"(p));
    return a;
}
DINL void cp_async16(uint32_t s, const void* g) {
    asm volatile("cp.async.cg.shared.global [%0], [%1], 16;" :: "r"(s), "l"(g));
}
DINL void cp_commit() { asm volatile("cp.async.commit_group;" ::: "memory"); }
template <int N> DINL void cp_wait() { asm volatile("cp.async.wait_group %0;" :: "n"(N) : "memory"); }

DINL void ldsm_x4(uint32_t* r, uint32_t addr) {
    asm volatile("ldmatrix.sync.aligned.m8n8.x4.shared.b16 {%0,%1,%2,%3}, [%4];"
                 : "=r"(r[0]), "=r"(r[1]), "=r"(r[2]), "=r"(r[3]) : "r"(addr));
}
DINL void mma_bf16(float* c, const uint32_t* a, const uint32_t* b) {
    asm volatile(
        "mma.sync.aligned.m16n8k16.row.col.f32.bf16.bf16.f32 "
        "{%0,%1,%2,%3}, {%4,%5,%6,%7}, {%8,%9}, {%0,%1,%2,%3};"
        : "+f"(c[0]), "+f"(c[1]), "+f"(c[2]), "+f"(c[3])
        : "r"(a[0]), "r"(a[1]), "r"(a[2]), "r"(a[3]), "r"(b[0]), "r"(b[1]));
}

// ---------------- fp32 -> bf16 hi/lo split ----------------
DINL void split_store(float4 x, __nv_bfloat16* hi, __nv_bfloat16* lo) {
    float xs[4] = {x.x, x.y, x.z, x.w};
    __nv_bfloat16 h[4], l[4];
#pragma unroll
    for (int i = 0; i < 4; ++i) {
        h[i] = __float2bfloat16(xs[i]);
        l[i] = __float2bfloat16(xs[i] - __bfloat162float(h[i]));
    }
    *reinterpret_cast<uint2*>(hi) = *reinterpret_cast<const uint2*>(h);
    *reinterpret_cast<uint2*>(lo) = *reinterpret_cast<const uint2*>(l);
}

// A = [hidden | enc] as [Mtot x Ktot] hi/lo bf16
__global__ void __launch_bounds__(256) k_convA(const float* __restrict__ hid,
                                               const float* __restrict__ enc) {
    size_t i = (size_t)blockIdx.x * blockDim.x + threadIdx.x;
    constexpr size_t TOT = (size_t)Mtot * Dn / 4;
    if (i >= TOT) return;
    size_t row = (i * 4) / Dn;
    size_t col = (i * 4) % Dn;
    float4 h = reinterpret_cast<const float4*>(hid)[i];
    float4 e = reinterpret_cast<const float4*>(enc)[i];
    size_t o = row * Ktot + col;
    split_store(h, g_Ahi + o, g_Alo + o);
    split_store(e, g_Ahi + o + Dn, g_Alo + o + Dn);
}

// Bcat[o][k] = k<1024 ? W[o][k] : W[o][2048 + (k-1024)]
__global__ void __launch_bounds__(256) k_convB(const float* __restrict__ W) {
    size_t i = (size_t)blockIdx.x * blockDim.x + threadIdx.x;
    constexpr size_t TOT = (size_t)On * Ktot / 4;
    if (i >= TOT) return;
    size_t o = (i * 4) / Ktot;
    size_t k = (i * 4) % Ktot;
    size_t src = o * (size_t)(3 * Dn) + (k < (size_t)Dn ? k : k + Dn);
    float4 w = *reinterpret_cast<const float4*>(W + src);
    split_store(w, g_Bhi + o * Ktot + k, g_Blo + o * Ktot + k);
}

// cb[b][o] = c_t[b] . W[o][1024:2048] + bias[o]   (one warp per output, fp32 exact)
__global__ void __launch_bounds__(256) k_cb(const float* __restrict__ ct,
                                            const float* __restrict__ W,
                                            const float* __restrict__ bias) {
    int gw = blockIdx.x * 8 + (threadIdx.x >> 5);
    int lane = threadIdx.x & 31;
    int b = gw >> 10;
    int o = gw & 1023;
    const float* c = ct + (size_t)b * Dn;
    const float* w = W + (size_t)o * (3 * Dn) + Dn;
    float s = 0.f;
    for (int k = lane; k < Dn; k += 32) s += c[k] * w[k];
#pragma unroll
    for (int off = 16; off; off >>= 1) s += __shfl_xor_sync(0xFFFFFFFFu, s, off);
    if (lane == 0) g_cb[b * On + o] = s + bias[o];
}

// ---------------- fused split-bf16 GEMM (mma.sync) + relu + dot(v) ----------------
DINL void load_stage(uint32_t stg, const __nv_bfloat16* Ah, const __nv_bfloat16* Al,
                     const __nv_bfloat16* Bh, const __nv_bfloat16* Bl, int kb, int tid) {
    // A: 256 rows x 4 chunks of 16B = 1024 chunks -> 2 iters of 512 threads
#pragma unroll
    for (int it = 0; it < 2; ++it) {
        int c = tid + it * THREADS;
        int row = c & 255, kc = c >> 8;                        // kc in 0..3
        uint32_t so = (uint32_t)(row * (ROW_PAD * 2) + kc * 16);
        size_t go = (size_t)row * Ktot + kb + kc * 8;
        cp_async16(stg + A_HI + so, Ah + go);
        cp_async16(stg + A_LO + so, Al + go);
    }
    // B: 128 rows x 4 chunks = 512 chunks -> 1 iter
    {
        int row = tid & 127, kc = tid >> 7;
        uint32_t so = (uint32_t)(row * (ROW_PAD * 2) + kc * 16);
        size_t go = (size_t)row * Ktot + kb + kc * 8;
        cp_async16(stg + B_HI + so, Bh + go);
        cp_async16(stg + B_LO + so, Bl + go);
    }
}

__global__ void __launch_bounds__(THREADS, 1) k_gemm(const float* __restrict__ v) {
    extern __shared__ char smem[];
    const uint32_t sb = smem_u32(smem);
    const int tid  = threadIdx.x;
    const int lane = tid & 31, wid = tid >> 5;
    const int wm = wid >> 2, wn = wid & 3;        // 4 x 4 warp grid, warp tile 64x32
    const int nch = blockIdx.x;                   // fast-varying: 8 CTAs share A via L2
    const int m_base = blockIdx.y * M_TILE;
    const int n_base = nch * N_TILE;
    const int bidx = m_base / Sn;                 // tile sits in one batch (256 | 2048)

    const __nv_bfloat16* Ah = g_Ahi + (size_t)m_base * Ktot;
    const __nv_bfloat16* Al = g_Alo + (size_t)m_base * Ktot;
    const __nv_bfloat16* Bh = g_Bhi + (size_t)n_base * Ktot;
    const __nv_bfloat16* Bl = g_Blo + (size_t)n_base * Ktot;

    // ldmatrix per-lane smem offsets (bytes within a stage array)
    const int r_in = lane & 7, grp = lane >> 3;
    uint32_t a_off[4], b_off[2];
#pragma unroll
    for (int mt = 0; mt < 4; ++mt) {
        int row = wm * 64 + mt * 16 + r_in + (grp & 1) * 8;   // groups 0/2: rows, 1/3: rows+8
        a_off[mt] = (uint32_t)(row * (ROW_PAD * 2) + ((grp >> 1) * 8) * 2);  // grp 2,3: k+8
    }
#pragma unroll
    for (int i = 0; i < 2; ++i) {
        int row = wn * 32 + i * 16 + r_in + (grp >> 1) * 8;   // groups 0/1: n, 2/3: n+8
        b_off[i] = (uint32_t)(row * (ROW_PAD * 2) + ((grp & 1) * 8) * 2);    // grp 1,3: k+8
    }

    float acc[4][4][4];
#pragma unroll
    for (int a = 0; a < 4; ++a)
#pragma unroll
        for (int b = 0; b < 4; ++b)
#pragma unroll
            for (int c = 0; c < 4; ++c) acc[a][b][c] = 0.f;

    load_stage(sb, Ah, Al, Bh, Bl, 0, tid);                       cp_commit();
    load_stage(sb + STAGE_BYTES, Ah, Al, Bh, Bl, K_TILE, tid);    cp_commit();

#pragma unroll 1
    for (int kt = 0; kt < KT; ++kt) {
        if (kt == KT - 1) cp_wait<0>(); else cp_wait<1>();
        __syncthreads();
        if (kt + 2 < KT) {
            load_stage(sb + (uint32_t)((kt + 2) % STAGES) * STAGE_BYTES,
                       Ah, Al, Bh, Bl, (kt + 2) * K_TILE, tid);
            cp_commit();
        }
        const uint32_t stg = sb + (uint32_t)(kt % STAGES) * STAGE_BYTES;
#pragma unroll
        for (int k16 = 0; k16 < 2; ++k16) {
            uint32_t bh[2][4], bl[2][4];
#pragma unroll
            for (int i = 0; i < 2; ++i) {
                ldsm_x4(bh[i], stg + B_HI + b_off[i] + k16 * 32);
                ldsm_x4(bl[i], stg + B_LO + b_off[i] + k16 * 32);
            }
            // stage A fragments per-mt to keep register pressure under 128
#pragma unroll
            for (int mt = 0; mt < 4; ++mt) {
                uint32_t ah[4], al[4];
                ldsm_x4(ah, stg + A_HI + a_off[mt] + k16 * 32);
                ldsm_x4(al, stg + A_LO + a_off[mt] + k16 * 32);
#pragma unroll
                for (int nt = 0; nt < 4; ++nt) {
                    const uint32_t* bhf = &bh[nt >> 1][(nt & 1) * 2];
                    const uint32_t* blf = &bl[nt >> 1][(nt & 1) * 2];
                    mma_bf16(acc[mt][nt], ah, bhf);   // hi*hi
                    mma_bf16(acc[mt][nt], ah, blf);   // hi*lo
                    mma_bf16(acc[mt][nt], al, bhf);   // lo*hi
                }
            }
        }
    }

    // ---- fused epilogue: partial[row] = sum_n relu(acc + cb[n]) * v[n] ----
    __syncthreads();                               // stages dead; reuse smem
    float* red = reinterpret_cast<float*>(smem);   // [256 rows][4 wn]
    const float* cbp = g_cb + bidx * On + n_base;
    const float* vp  = v + n_base;
    float cbv[4][2], vv[4][2];
#pragma unroll
    for (int nt = 0; nt < 4; ++nt)
#pragma unroll
        for (int j = 0; j < 2; ++j) {
            int n = wn * 32 + nt * 8 + 2 * (lane & 3) + j;
            cbv[nt][j] = cbp[n];
            vv[nt][j]  = vp[n];
        }
#pragma unroll
    for (int mt = 0; mt < 4; ++mt)
#pragma unroll
        for (int h = 0; h < 2; ++h) {
            float s = 0.f;
#pragma unroll
            for (int nt = 0; nt < 4; ++nt)
#pragma unroll
                for (int j = 0; j < 2; ++j) {
                    float e = acc[mt][nt][2 * h + j] + cbv[nt][j];
                    s += fmaxf(e, 0.f) * vv[nt][j];
                }
            s += __shfl_xor_sync(0xFFFFFFFFu, s, 1);
            s += __shfl_xor_sync(0xFFFFFFFFu, s, 2);
            if ((lane & 3) == 0) {
                int row = wm * 64 + mt * 16 + (lane >> 2) + 8 * h;
                red[row * 4 + wn] = s;
            }
        }
    __syncthreads();
    if (tid < M_TILE) {
        float sum = red[tid * 4] + red[tid * 4 + 1] + red[tid * 4 + 2] + red[tid * 4 + 3];
        g_part[nch][m_base + tid] = sum;
    }
}

// ---------------- softmax over S per batch ----------------
__global__ void __launch_bounds__(1024) k_softmax(float* __restrict__ out) {
    __shared__ float red[32];
    const int b = blockIdx.x;
    const int t = threadIdx.x;
    const int i0 = b * Sn + t;
    const int i1 = i0 + 1024;
    float l0 = 0.f, l1 = 0.f;
#pragma unroll
    for (int c = 0; c < NCH; ++c) { l0 += g_part[c][i0]; l1 += g_part[c][i1]; }

    float m = fmaxf(l0, l1);
#pragma unroll
    for (int off = 16; off; off >>= 1) m = fmaxf(m, __shfl_xor_sync(0xFFFFFFFFu, m, off));
    if ((t & 31) == 0) red[t >> 5] = m;
    __syncthreads();
    if (t < 32) {
        float x = red[t];
#pragma unroll
        for (int off = 16; off; off >>= 1) x = fmaxf(x, __shfl_xor_sync(0xFFFFFFFFu, x, off));
        if (t == 0) red[0] = x;
    }
    __syncthreads();
    const float M = red[0];
    __syncthreads();

    float e0 = expf(l0 - M), e1 = expf(l1 - M);
    float s = e0 + e1;
#pragma unroll
    for (int off = 16; off; off >>= 1) s += __shfl_xor_sync(0xFFFFFFFFu, s, off);
    if ((t & 31) == 0) red[t >> 5] = s;
    __syncthreads();
    if (t < 32) {
        float x = red[t];
#pragma unroll
        for (int off = 16; off; off >>= 1) x += __shfl_xor_sync(0xFFFFFFFFu, x, off);
        if (t == 0) red[0] = x;
    }
    __syncthreads();
    const float inv = 1.0f / red[0];
    out[i0] = e0 * inv;
    out[i1] = e1 * inv;
}

// ---------------- launch ----------------
extern "C" void kernel_launch(void* const* d_in, const int* in_sizes, int n_in,
                              void* d_out, int out_size) {
    const float* hid  = (const float*)d_in[0];   // [16,2048,1024]
    const float* enc  = (const float*)d_in[1];   // [16,2048,1024]
    const float* ct   = (const float*)d_in[2];   // [16,1024]
    const float* W    = (const float*)d_in[3];   // [1024,3072]
    const float* bias = (const float*)d_in[4];   // [1024]
    const float* v    = (const float*)d_in[5];   // [1024]
    float* out = (float*)d_out;                  // [16,2048]

    cudaFuncSetAttribute(k_gemm, cudaFuncAttributeMaxDynamicSharedMemorySize, SMEM_TOTAL);

    k_convA<<<(unsigned)((size_t)Mtot * Dn / 4 / 256), 256>>>(hid, enc);
    k_convB<<<(unsigned)((size_t)On * Ktot / 4 / 256), 256>>>(W);
    k_cb<<<Bn * On / 8, 256>>>(ct, W, bias);
    dim3 grid(NCH, MT);
    k_gemm<<<grid, THREADS, SMEM_TOTAL>>>(v);
    k_softmax<<<Bn, 1024>>>(out);
}

// round 9
// speedup vs baseline: 1.2315x; 1.0009x over previous
#include <cuda_runtime.h>
#include <cuda_bf16.h>
#include <cstdint>
#include <cstddef>

#define DINL __device__ __forceinline__

// ---------------- problem constants ----------------
namespace {
constexpr int Bn = 16, Sn = 2048, Dn = 1024, On = 1024;
constexpr int Mtot = Bn * Sn;           // 32768 rows
constexpr int Ktot = 2 * Dn;            // 2048 (hidden | enc concat)
constexpr int M_TILE = 256, N_TILE = 128, K_TILE = 32;
constexpr int KT  = Ktot / K_TILE;      // 64 k-iterations
constexpr int NCH = On / N_TILE;        // 8 n-chunks
constexpr int MT  = Mtot / M_TILE;      // 128 m-tiles
constexpr int THREADS = 512;            // 16 warps: 4 (M) x 4 (N), warp tile 64x32

// smem: padded rows -> conflict-free ldmatrix & cp.async stores
constexpr int ROW_PAD = 40;                         // halves per 32-half row (80 B)
constexpr int A_ARR = M_TILE * ROW_PAD * 2;         // 20480 B per A operand array
constexpr int B_ARR = N_TILE * ROW_PAD * 2;         // 10240 B per B operand array
constexpr int A_HI = 0, A_LO = A_ARR;
constexpr int B_HI = 2 * A_ARR, B_LO = 2 * A_ARR + B_ARR;
constexpr int STAGE_BYTES = 2 * A_ARR + 2 * B_ARR;  // 61440 B
constexpr int STAGES = 3;
constexpr int SMEM_TOTAL = STAGES * STAGE_BYTES;    // 184320 B (fits 227KB)
}

// ---------------- scratch (device globals; no allocs allowed) ----------------
__device__ __nv_bfloat16 g_Ahi[(size_t)Mtot * Ktot];   // 128 MB
__device__ __nv_bfloat16 g_Alo[(size_t)Mtot * Ktot];   // 128 MB
__device__ __nv_bfloat16 g_Bhi[(size_t)On * Ktot];     // 4 MB
__device__ __nv_bfloat16 g_Blo[(size_t)On * Ktot];     // 4 MB
__device__ float g_cb[Bn * On];                        // c_t @ W2^T + bias
__device__ float g_part[NCH][Mtot];                    // per-n-chunk logit partials

// ---------------- PTX helpers (base sm_80+ only; no tcgen05 on sm_103 base) ----
DINL uint32_t smem_u32(const void* p) {
    uint32_t a;
    asm("{ .reg .u64 t; cvta.to.shared.u64 t, %1; cvt.u32.u64 %0, t; }" : "=r"(a) : "l"(p));
    return a;
}
DINL void cp_async16(uint32_t s, const void* g) {
    asm volatile("cp.async.cg.shared.global [%0], [%1], 16;" :: "r"(s), "l"(g));
}
DINL void cp_commit() { asm volatile("cp.async.commit_group;" ::: "memory"); }
template <int N> DINL void cp_wait() { asm volatile("cp.async.wait_group %0;" :: "n"(N) : "memory"); }

DINL void ldsm_x4(uint32_t* r, uint32_t addr) {
    asm volatile("ldmatrix.sync.aligned.m8n8.x4.shared.b16 {%0,%1,%2,%3}, [%4];"
                 : "=r"(r[0]), "=r"(r[1]), "=r"(r[2]), "=r"(r[3]) : "r"(addr));
}
DINL void mma_bf16(float* c, const uint32_t* a, const uint32_t* b) {
    asm volatile(
        "mma.sync.aligned.m16n8k16.row.col.f32.bf16.bf16.f32 "
        "{%0,%1,%2,%3}, {%4,%5,%6,%7}, {%8,%9}, {%0,%1,%2,%3};"
        : "+f"(c[0]), "+f"(c[1]), "+f"(c[2]), "+f"(c[3])
        : "r"(a[0]), "r"(a[1]), "r"(a[2]), "r"(a[3]), "r"(b[0]), "r"(b[1]));
}

// ---------------- fp32 -> bf16 hi/lo split ----------------
DINL void split_store(float4 x, __nv_bfloat16* hi, __nv_bfloat16* lo) {
    float xs[4] = {x.x, x.y, x.z, x.w};
    __nv_bfloat16 h[4], l[4];
#pragma unroll
    for (int i = 0; i < 4; ++i) {
        h[i] = __float2bfloat16(xs[i]);
        l[i] = __float2bfloat16(xs[i] - __bfloat162float(h[i]));
    }
    *reinterpret_cast<uint2*>(hi) = *reinterpret_cast<const uint2*>(h);
    *reinterpret_cast<uint2*>(lo) = *reinterpret_cast<const uint2*>(l);
}

// A = [hidden | enc] as [Mtot x Ktot] hi/lo bf16
__global__ void __launch_bounds__(256) k_convA(const float* __restrict__ hid,
                                               const float* __restrict__ enc) {
    size_t i = (size_t)blockIdx.x * blockDim.x + threadIdx.x;
    constexpr size_t TOT = (size_t)Mtot * Dn / 4;
    if (i >= TOT) return;
    size_t row = (i * 4) / Dn;
    size_t col = (i * 4) % Dn;
    float4 h = reinterpret_cast<const float4*>(hid)[i];
    float4 e = reinterpret_cast<const float4*>(enc)[i];
    size_t o = row * Ktot + col;
    split_store(h, g_Ahi + o, g_Alo + o);
    split_store(e, g_Ahi + o + Dn, g_Alo + o + Dn);
}

// Bcat[o][k] = k<1024 ? W[o][k] : W[o][2048 + (k-1024)]
__global__ void __launch_bounds__(256) k_convB(const float* __restrict__ W) {
    size_t i = (size_t)blockIdx.x * blockDim.x + threadIdx.x;
    constexpr size_t TOT = (size_t)On * Ktot / 4;
    if (i >= TOT) return;
    size_t o = (i * 4) / Ktot;
    size_t k = (i * 4) % Ktot;
    size_t src = o * (size_t)(3 * Dn) + (k < (size_t)Dn ? k : k + Dn);
    float4 w = *reinterpret_cast<const float4*>(W + src);
    split_store(w, g_Bhi + o * Ktot + k, g_Blo + o * Ktot + k);
}

// cb[b][o] = c_t[b] . W[o][1024:2048] + bias[o]   (one warp per output, fp32 exact)
__global__ void __launch_bounds__(256) k_cb(const float* __restrict__ ct,
                                            const float* __restrict__ W,
                                            const float* __restrict__ bias) {
    int gw = blockIdx.x * 8 + (threadIdx.x >> 5);
    int lane = threadIdx.x & 31;
    int b = gw >> 10;
    int o = gw & 1023;
    const float* c = ct + (size_t)b * Dn;
    const float* w = W + (size_t)o * (3 * Dn) + Dn;
    float s = 0.f;
    for (int k = lane; k < Dn; k += 32) s += c[k] * w[k];
#pragma unroll
    for (int off = 16; off; off >>= 1) s += __shfl_xor_sync(0xFFFFFFFFu, s, off);
    if (lane == 0) g_cb[b * On + o] = s + bias[o];
}

// ---------------- fused split-bf16 GEMM (mma.sync) + relu + dot(v) ----------------
DINL void load_stage(uint32_t stg, const __nv_bfloat16* Ah, const __nv_bfloat16* Al,
                     const __nv_bfloat16* Bh, const __nv_bfloat16* Bl, int kb, int tid) {
    // A: 256 rows x 4 chunks of 16B = 1024 chunks -> 2 iters of 512 threads
#pragma unroll
    for (int it = 0; it < 2; ++it) {
        int c = tid + it * THREADS;
        int row = c & 255, kc = c >> 8;                        // kc in 0..3
        uint32_t so = (uint32_t)(row * (ROW_PAD * 2) + kc * 16);
        size_t go = (size_t)row * Ktot + kb + kc * 8;
        cp_async16(stg + A_HI + so, Ah + go);
        cp_async16(stg + A_LO + so, Al + go);
    }
    // B: 128 rows x 4 chunks = 512 chunks -> 1 iter
    {
        int row = tid & 127, kc = tid >> 7;
        uint32_t so = (uint32_t)(row * (ROW_PAD * 2) + kc * 16);
        size_t go = (size_t)row * Ktot + kb + kc * 8;
        cp_async16(stg + B_HI + so, Bh + go);
        cp_async16(stg + B_LO + so, Bl + go);
    }
}

__global__ void __launch_bounds__(THREADS, 1) k_gemm(const float* __restrict__ v) {
    extern __shared__ char smem[];
    const uint32_t sb = smem_u32(smem);
    const int tid  = threadIdx.x;
    const int lane = tid & 31, wid = tid >> 5;
    const int wm = wid >> 2, wn = wid & 3;        // 4 x 4 warp grid, warp tile 64x32
    const int nch = blockIdx.x;                   // fast-varying: 8 CTAs share A via L2
    const int m_base = blockIdx.y * M_TILE;
    const int n_base = nch * N_TILE;
    const int bidx = m_base / Sn;                 // tile sits in one batch (256 | 2048)

    const __nv_bfloat16* Ah = g_Ahi + (size_t)m_base * Ktot;
    const __nv_bfloat16* Al = g_Alo + (size_t)m_base * Ktot;
    const __nv_bfloat16* Bh = g_Bhi + (size_t)n_base * Ktot;
    const __nv_bfloat16* Bl = g_Blo + (size_t)n_base * Ktot;

    // ldmatrix per-lane smem offsets (bytes within a stage array)
    const int r_in = lane & 7, grp = lane >> 3;
    uint32_t a_off[4], b_off[2];
#pragma unroll
    for (int mt = 0; mt < 4; ++mt) {
        int row = wm * 64 + mt * 16 + r_in + (grp & 1) * 8;   // groups 0/2: rows, 1/3: rows+8
        a_off[mt] = (uint32_t)(row * (ROW_PAD * 2) + ((grp >> 1) * 8) * 2);  // grp 2,3: k+8
    }
#pragma unroll
    for (int i = 0; i < 2; ++i) {
        int row = wn * 32 + i * 16 + r_in + (grp >> 1) * 8;   // groups 0/1: n, 2/3: n+8
        b_off[i] = (uint32_t)(row * (ROW_PAD * 2) + ((grp & 1) * 8) * 2);    // grp 1,3: k+8
    }

    float acc[4][4][4];
#pragma unroll
    for (int a = 0; a < 4; ++a)
#pragma unroll
        for (int b = 0; b < 4; ++b)
#pragma unroll
            for (int c = 0; c < 4; ++c) acc[a][b][c] = 0.f;

    load_stage(sb, Ah, Al, Bh, Bl, 0, tid);                       cp_commit();
    load_stage(sb + STAGE_BYTES, Ah, Al, Bh, Bl, K_TILE, tid);    cp_commit();

#pragma unroll 1
    for (int kt = 0; kt < KT; ++kt) {
        if (kt == KT - 1) cp_wait<0>(); else cp_wait<1>();
        __syncthreads();
        if (kt + 2 < KT) {
            load_stage(sb + (uint32_t)((kt + 2) % STAGES) * STAGE_BYTES,
                       Ah, Al, Bh, Bl, (kt + 2) * K_TILE, tid);
            cp_commit();
        }
        const uint32_t stg = sb + (uint32_t)(kt % STAGES) * STAGE_BYTES;
#pragma unroll
        for (int k16 = 0; k16 < 2; ++k16) {
            // B fragments for this k16
            uint32_t bh[2][4], bl[2][4];
            ldsm_x4(bh[0], stg + B_HI + b_off[0] + k16 * 32);
            ldsm_x4(bl[0], stg + B_LO + b_off[0] + k16 * 32);
            ldsm_x4(bh[1], stg + B_HI + b_off[1] + k16 * 32);
            ldsm_x4(bl[1], stg + B_LO + b_off[1] + k16 * 32);
            // software-pipelined A fragments: prefetch A[mt+1] before MMAs of A[mt]
            uint32_t ah[2][4], al[2][4];
            ldsm_x4(ah[0], stg + A_HI + a_off[0] + k16 * 32);
            ldsm_x4(al[0], stg + A_LO + a_off[0] + k16 * 32);
#pragma unroll
            for (int mt = 0; mt < 4; ++mt) {
                const int cur = mt & 1, nxt = cur ^ 1;
                if (mt < 3) {
                    ldsm_x4(ah[nxt], stg + A_HI + a_off[mt + 1] + k16 * 32);
                    ldsm_x4(al[nxt], stg + A_LO + a_off[mt + 1] + k16 * 32);
                }
#pragma unroll
                for (int nt = 0; nt < 4; ++nt) {
                    const uint32_t* bhf = &bh[nt >> 1][(nt & 1) * 2];
                    const uint32_t* blf = &bl[nt >> 1][(nt & 1) * 2];
                    mma_bf16(acc[mt][nt], ah[cur], bhf);   // hi*hi
                    mma_bf16(acc[mt][nt], ah[cur], blf);   // hi*lo
                    mma_bf16(acc[mt][nt], al[cur], bhf);   // lo*hi
                }
            }
        }
    }

    // ---- fused epilogue: partial[row] = sum_n relu(acc + cb[n]) * v[n] ----
    __syncthreads();                               // stages dead; reuse smem
    float* red = reinterpret_cast<float*>(smem);   // [256 rows][4 wn]
    const float* cbp = g_cb + bidx * On + n_base;
    const float* vp  = v + n_base;
    float cbv[4][2], vv[4][2];
#pragma unroll
    for (int nt = 0; nt < 4; ++nt)
#pragma unroll
        for (int j = 0; j < 2; ++j) {
            int n = wn * 32 + nt * 8 + 2 * (lane & 3) + j;
            cbv[nt][j] = cbp[n];
            vv[nt][j]  = vp[n];
        }
#pragma unroll
    for (int mt = 0; mt < 4; ++mt)
#pragma unroll
        for (int h = 0; h < 2; ++h) {
            float s = 0.f;
#pragma unroll
            for (int nt = 0; nt < 4; ++nt)
#pragma unroll
                for (int j = 0; j < 2; ++j) {
                    float e = acc[mt][nt][2 * h + j] + cbv[nt][j];
                    s += fmaxf(e, 0.f) * vv[nt][j];
                }
            s += __shfl_xor_sync(0xFFFFFFFFu, s, 1);
            s += __shfl_xor_sync(0xFFFFFFFFu, s, 2);
            if ((lane & 3) == 0) {
                int row = wm * 64 + mt * 16 + (lane >> 2) + 8 * h;
                red[row * 4 + wn] = s;
            }
        }
    __syncthreads();
    if (tid < M_TILE) {
        float sum = red[tid * 4] + red[tid * 4 + 1] + red[tid * 4 + 2] + red[tid * 4 + 3];
        g_part[nch][m_base + tid] = sum;
    }
}

// ---------------- softmax over S per batch ----------------
__global__ void __launch_bounds__(1024) k_softmax(float* __restrict__ out) {
    __shared__ float red[32];
    const int b = blockIdx.x;
    const int t = threadIdx.x;
    const int i0 = b * Sn + t;
    const int i1 = i0 + 1024;
    float l0 = 0.f, l1 = 0.f;
#pragma unroll
    for (int c = 0; c < NCH; ++c) { l0 += g_part[c][i0]; l1 += g_part[c][i1]; }

    float m = fmaxf(l0, l1);
#pragma unroll
    for (int off = 16; off; off >>= 1) m = fmaxf(m, __shfl_xor_sync(0xFFFFFFFFu, m, off));
    if ((t & 31) == 0) red[t >> 5] = m;
    __syncthreads();
    if (t < 32) {
        float x = red[t];
#pragma unroll
        for (int off = 16; off; off >>= 1) x = fmaxf(x, __shfl_xor_sync(0xFFFFFFFFu, x, off));
        if (t == 0) red[0] = x;
    }
    __syncthreads();
    const float M = red[0];
    __syncthreads();

    float e0 = expf(l0 - M), e1 = expf(l1 - M);
    float s = e0 + e1;
#pragma unroll
    for (int off = 16; off; off >>= 1) s += __shfl_xor_sync(0xFFFFFFFFu, s, off);
    if ((t & 31) == 0) red[t >> 5] = s;
    __syncthreads();
    if (t < 32) {
        float x = red[t];
#pragma unroll
        for (int off = 16; off; off >>= 1) x += __shfl_xor_sync(0xFFFFFFFFu, x, off);
        if (t == 0) red[0] = x;
    }
    __syncthreads();
    const float inv = 1.0f / red[0];
    out[i0] = e0 * inv;
    out[i1] = e1 * inv;
}

// ---------------- launch ----------------
extern "C" void kernel_launch(void* const* d_in, const int* in_sizes, int n_in,
                              void* d_out, int out_size) {
    const float* hid  = (const float*)d_in[0];   // [16,2048,1024]
    const float* enc  = (const float*)d_in[1];   // [16,2048,1024]
    const float* ct   = (const float*)d_in[2];   // [16,1024]
    const float* W    = (const float*)d_in[3];   // [1024,3072]
    const float* bias = (const float*)d_in[4];   // [1024]
    const float* v    = (const float*)d_in[5];   // [1024]
    float* out = (float*)d_out;                  // [16,2048]

    cudaFuncSetAttribute(k_gemm, cudaFuncAttributeMaxDynamicSharedMemorySize, SMEM_TOTAL);

    k_convA<<<(unsigned)((size_t)Mtot * Dn / 4 / 256), 256>>>(hid, enc);
    k_convB<<<(unsigned)((size_t)On * Ktot / 4 / 256), 256>>>(W);
    k_cb<<<Bn * On / 8, 256>>>(ct, W, bias);
    dim3 grid(NCH, MT);
    k_gemm<<<grid, THREADS, SMEM_TOTAL>>>(v);
    k_softmax<<<Bn, 1024>>>(out);
}

// round 13
// speedup vs baseline: 1.4172x; 1.1508x over previous
#include <cuda_runtime.h>
#include <cuda_bf16.h>
#include <cstdint>
#include <cstddef>

#define DINL __device__ __forceinline__

// ---------------- problem constants ----------------
namespace {
constexpr int Bn = 16, Sn = 2048, Dn = 1024, On = 1024;
constexpr int Mtot = Bn * Sn;           // 32768 rows
constexpr int Ktot = 2 * Dn;            // 2048 (hidden | enc concat)
constexpr int M_TILE = 128, N_TILE = 128, K_TILE = 32;
constexpr int KT  = Ktot / K_TILE;      // 64 k-iterations
constexpr int NCH = On / N_TILE;        // 8 n-chunks
constexpr int MT  = Mtot / M_TILE;      // 256 m-tiles
constexpr int THREADS = 256;            // 8 warps: 2 (M) x 4 (N), warp tile 64x32

// smem: padded rows -> conflict-free ldmatrix & cp.async stores
constexpr int ROW_PAD = 40;                         // halves per 32-half row (80 B)
constexpr int ARR = 128 * ROW_PAD * 2;              // 10240 B per operand array
constexpr int A_HI = 0, A_LO = ARR, B_HI = 2 * ARR, B_LO = 3 * ARR;
constexpr int STAGE_BYTES = 4 * ARR;                // 40960 B
constexpr int STAGES = 2;
constexpr int SMEM_TOTAL = STAGES * STAGE_BYTES;    // 81920 B -> 2 CTAs/SM
constexpr int CHUNKS = 2048;                        // 16B chunks per stage
}

// ---------------- scratch (device globals; no allocs allowed) ----------------
__device__ __nv_bfloat16 g_Ahi[(size_t)Mtot * Ktot];   // 128 MB
__device__ __nv_bfloat16 g_Alo[(size_t)Mtot * Ktot];   // 128 MB
__device__ __nv_bfloat16 g_Bhi[(size_t)On * Ktot];     // 4 MB
__device__ __nv_bfloat16 g_Blo[(size_t)On * Ktot];     // 4 MB
__device__ float g_cb[Bn * On];                        // c_t @ W2^T + bias
__device__ float g_part[NCH][Mtot];                    // per-n-chunk logit partials

// ---------------- PTX helpers (base sm_80+ only; no tcgen05 on sm_103 base) ----
DINL uint32_t smem_u32(const void* p) {
    uint32_t a;
    asm("{ .reg .u64 t; cvta.to.shared.u64 t, %1; cvt.u32.u64 %0, t; }" : "=r"(a) : "l"(p));
    return a;
}
DINL void cp_async16(uint32_t s, const void* g) {
    asm volatile("cp.async.cg.shared.global [%0], [%1], 16;" :: "r"(s), "l"(g));
}
DINL void cp_commit() { asm volatile("cp.async.commit_group;" ::: "memory"); }
template <int N> DINL void cp_wait() { asm volatile("cp.async.wait_group %0;" :: "n"(N) : "memory"); }

DINL void ldsm_x4(uint32_t* r, uint32_t addr) {
    asm volatile("ldmatrix.sync.aligned.m8n8.x4.shared.b16 {%0,%1,%2,%3}, [%4];"
                 : "=r"(r[0]), "=r"(r[1]), "=r"(r[2]), "=r"(r[3]) : "r"(addr));
}
DINL void mma_bf16(float* c, const uint32_t* a, const uint32_t* b) {
    asm volatile(
        "mma.sync.aligned.m16n8k16.row.col.f32.bf16.bf16.f32 "
        "{%0,%1,%2,%3}, {%4,%5,%6,%7}, {%8,%9}, {%0,%1,%2,%3};"
        : "+f"(c[0]), "+f"(c[1]), "+f"(c[2]), "+f"(c[3])
        : "r"(a[0]), "r"(a[1]), "r"(a[2]), "r"(a[3]), "r"(b[0]), "r"(b[1]));
}

// ---------------- fp32 -> bf16 hi/lo split ----------------
DINL void split_store(float4 x, __nv_bfloat16* hi, __nv_bfloat16* lo) {
    float xs[4] = {x.x, x.y, x.z, x.w};
    __nv_bfloat16 h[4], l[4];
#pragma unroll
    for (int i = 0; i < 4; ++i) {
        h[i] = __float2bfloat16(xs[i]);
        l[i] = __float2bfloat16(xs[i] - __bfloat162float(h[i]));
    }
    *reinterpret_cast<uint2*>(hi) = *reinterpret_cast<const uint2*>(h);
    *reinterpret_cast<uint2*>(lo) = *reinterpret_cast<const uint2*>(l);
}

// A = [hidden | enc] as [Mtot x Ktot] hi/lo bf16
__global__ void __launch_bounds__(256) k_convA(const float* __restrict__ hid,
                                               const float* __restrict__ enc) {
    size_t i = (size_t)blockIdx.x * blockDim.x + threadIdx.x;
    constexpr size_t TOT = (size_t)Mtot * Dn / 4;
    if (i >= TOT) return;
    size_t row = (i * 4) / Dn;
    size_t col = (i * 4) % Dn;
    float4 h = reinterpret_cast<const float4*>(hid)[i];
    float4 e = reinterpret_cast<const float4*>(enc)[i];
    size_t o = row * Ktot + col;
    split_store(h, g_Ahi + o, g_Alo + o);
    split_store(e, g_Ahi + o + Dn, g_Alo + o + Dn);
}

// Bcat[o][k] = k<1024 ? W[o][k] : W[o][2048 + (k-1024)]
__global__ void __launch_bounds__(256) k_convB(const float* __restrict__ W) {
    size_t i = (size_t)blockIdx.x * blockDim.x + threadIdx.x;
    constexpr size_t TOT = (size_t)On * Ktot / 4;
    if (i >= TOT) return;
    size_t o = (i * 4) / Ktot;
    size_t k = (i * 4) % Ktot;
    size_t src = o * (size_t)(3 * Dn) + (k < (size_t)Dn ? k : k + Dn);
    float4 w = *reinterpret_cast<const float4*>(W + src);
    split_store(w, g_Bhi + o * Ktot + k, g_Blo + o * Ktot + k);
}

// cb[b][o] = c_t[b] . W[o][1024:2048] + bias[o]   (one warp per output, fp32 exact)
__global__ void __launch_bounds__(256) k_cb(const float* __restrict__ ct,
                                            const float* __restrict__ W,
                                            const float* __restrict__ bias) {
    int gw = blockIdx.x * 8 + (threadIdx.x >> 5);
    int lane = threadIdx.x & 31;
    int b = gw >> 10;
    int o = gw & 1023;
    const float* c = ct + (size_t)b * Dn;
    const float* w = W + (size_t)o * (3 * Dn) + Dn;
    float s = 0.f;
    for (int k = lane; k < Dn; k += 32) s += c[k] * w[k];
#pragma unroll
    for (int off = 16; off; off >>= 1) s += __shfl_xor_sync(0xFFFFFFFFu, s, off);
    if (lane == 0) g_cb[b * On + o] = s + bias[o];
}

// ---------------- fused split-bf16 GEMM (mma.sync) + relu + dot(v) ----------------
// one 16B chunk of a stage: cid in [0, 2048); arrays uniform per warp
DINL void load_chunk(uint32_t stg, const __nv_bfloat16* Ah, const __nv_bfloat16* Al,
                     const __nv_bfloat16* Bh, const __nv_bfloat16* Bl, int kb, int cid) {
    const int arr = cid >> 9;                 // 0:Ahi 1:Alo 2:Bhi 3:Blo
    const int c = cid & 511;
    const int row = c & 127, kc = c >> 7;     // kc in 0..3
    const uint32_t so = (uint32_t)(arr * ARR + row * (ROW_PAD * 2) + kc * 16);
    const size_t go = (size_t)row * Ktot + kb + kc * 8;
    const __nv_bfloat16* src = (arr == 0) ? Ah : (arr == 1) ? Al : (arr == 2) ? Bh : Bl;
    cp_async16(stg + so, src + go);
}

__global__ void __launch_bounds__(THREADS, 2) k_gemm(const float* __restrict__ v) {
    extern __shared__ char smem[];
    const uint32_t sb = smem_u32(smem);
    const int tid  = threadIdx.x;
    const int lane = tid & 31, wid = tid >> 5;
    const int wm = wid >> 2, wn = wid & 3;        // 2 x 4 warp grid, warp tile 64x32
    const int nch = blockIdx.x;                   // fast-varying: 8 CTAs share A via L2
    const int m_base = blockIdx.y * M_TILE;
    const int n_base = nch * N_TILE;
    const int bidx = m_base / Sn;                 // tile sits in one batch (128 | 2048)

    const __nv_bfloat16* Ah = g_Ahi + (size_t)m_base * Ktot;
    const __nv_bfloat16* Al = g_Alo + (size_t)m_base * Ktot;
    const __nv_bfloat16* Bh = g_Bhi + (size_t)n_base * Ktot;
    const __nv_bfloat16* Bl = g_Blo + (size_t)n_base * Ktot;

    // ldmatrix per-lane smem offsets (bytes within a stage array)
    const int r_in = lane & 7, grp = lane >> 3;
    uint32_t a_off[4], b_off[2];
#pragma unroll
    for (int mt = 0; mt < 4; ++mt) {
        int row = wm * 64 + mt * 16 + r_in + (grp & 1) * 8;   // groups 0/2: rows, 1/3: rows+8
        a_off[mt] = (uint32_t)(row * (ROW_PAD * 2) + ((grp >> 1) * 8) * 2);  // grp 2,3: k+8
    }
#pragma unroll
    for (int i = 0; i < 2; ++i) {
        int row = wn * 32 + i * 16 + r_in + (grp >> 1) * 8;   // groups 0/1: n, 2/3: n+8
        b_off[i] = (uint32_t)(row * (ROW_PAD * 2) + ((grp & 1) * 8) * 2);    // grp 1,3: k+8
    }

    float acc[4][4][4];
#pragma unroll
    for (int a = 0; a < 4; ++a)
#pragma unroll
        for (int b = 0; b < 4; ++b)
#pragma unroll
            for (int c = 0; c < 4; ++c) acc[a][b][c] = 0.f;

    // prologue: fill stage 0
#pragma unroll
    for (int j = 0; j < CHUNKS / THREADS; ++j)
        load_chunk(sb, Ah, Al, Bh, Bl, 0, j * THREADS + tid);
    cp_commit();

#pragma unroll 1
    for (int kt = 0; kt < KT; ++kt) {
        cp_wait<0>();
        __syncthreads();
        const uint32_t stg  = sb + (uint32_t)(kt & 1) * STAGE_BYTES;
        const uint32_t nstg = sb + (uint32_t)((kt + 1) & 1) * STAGE_BYTES;
        const bool pf = (kt + 1 < KT);
        const int nkb = (kt + 1) * K_TILE;
#pragma unroll
        for (int k16 = 0; k16 < 2; ++k16) {
            // B fragments for this k16
            uint32_t bh[2][4], bl[2][4];
            ldsm_x4(bh[0], stg + B_HI + b_off[0] + k16 * 32);
            ldsm_x4(bl[0], stg + B_LO + b_off[0] + k16 * 32);
            ldsm_x4(bh[1], stg + B_HI + b_off[1] + k16 * 32);
            ldsm_x4(bl[1], stg + B_LO + b_off[1] + k16 * 32);
            // software-pipelined A fragments
            uint32_t ah[2][4], al[2][4];
            ldsm_x4(ah[0], stg + A_HI + a_off[0] + k16 * 32);
            ldsm_x4(al[0], stg + A_LO + a_off[0] + k16 * 32);
#pragma unroll
            for (int mt = 0; mt < 4; ++mt) {
                const int cur = mt & 1, nxt = cur ^ 1;
                if (mt < 3) {
                    ldsm_x4(ah[nxt], stg + A_HI + a_off[mt + 1] + k16 * 32);
                    ldsm_x4(al[nxt], stg + A_LO + a_off[mt + 1] + k16 * 32);
                }
                // spread next-stage prefetch through first 4 inner iterations
                const int it = k16 * 4 + mt;
                if (pf && it < 4) {
                    load_chunk(nstg, Ah, Al, Bh, Bl, nkb, (2 * it) * THREADS + tid);
                    load_chunk(nstg, Ah, Al, Bh, Bl, nkb, (2 * it + 1) * THREADS + tid);
                }
#pragma unroll
                for (int nt = 0; nt < 4; ++nt) {
                    const uint32_t* bhf = &bh[nt >> 1][(nt & 1) * 2];
                    const uint32_t* blf = &bl[nt >> 1][(nt & 1) * 2];
                    mma_bf16(acc[mt][nt], ah[cur], bhf);   // hi*hi
                    mma_bf16(acc[mt][nt], ah[cur], blf);   // hi*lo
                    mma_bf16(acc[mt][nt], al[cur], bhf);   // lo*hi
                }
            }
        }
        cp_commit();
    }

    // ---- fused epilogue: partial[row] = sum_n relu(acc + cb[n]) * v[n] ----
    __syncthreads();                               // stages dead; reuse smem
    float* red = reinterpret_cast<float*>(smem);   // [128 rows][4 wn]
    const float* cbp = g_cb + bidx * On + n_base;
    const float* vp  = v + n_base;
    float cbv[4][2], vv[4][2];
#pragma unroll
    for (int nt = 0; nt < 4; ++nt)
#pragma unroll
        for (int j = 0; j < 2; ++j) {
            int n = wn * 32 + nt * 8 + 2 * (lane & 3) + j;
            cbv[nt][j] = cbp[n];
            vv[nt][j]  = vp[n];
        }
#pragma unroll
    for (int mt = 0; mt < 4; ++mt)
#pragma unroll
        for (int h = 0; h < 2; ++h) {
            float s = 0.f;
#pragma unroll
            for (int nt = 0; nt < 4; ++nt)
#pragma unroll
                for (int j = 0; j < 2; ++j) {
                    float e = acc[mt][nt][2 * h + j] + cbv[nt][j];
                    s += fmaxf(e, 0.f) * vv[nt][j];
                }
            s += __shfl_xor_sync(0xFFFFFFFFu, s, 1);
            s += __shfl_xor_sync(0xFFFFFFFFu, s, 2);
            if ((lane & 3) == 0) {
                int row = wm * 64 + mt * 16 + (lane >> 2) + 8 * h;
                red[row * 4 + wn] = s;
            }
        }
    __syncthreads();
    if (tid < M_TILE) {
        float sum = red[tid * 4] + red[tid * 4 + 1] + red[tid * 4 + 2] + red[tid * 4 + 3];
        g_part[nch][m_base + tid] = sum;
    }
}

// ---------------- softmax over S per batch ----------------
__global__ void __launch_bounds__(1024) k_softmax(float* __restrict__ out) {
    __shared__ float red[32];
    const int b = blockIdx.x;
    const int t = threadIdx.x;
    const int i0 = b * Sn + t;
    const int i1 = i0 + 1024;
    float l0 = 0.f, l1 = 0.f;
#pragma unroll
    for (int c = 0; c < NCH; ++c) { l0 += g_part[c][i0]; l1 += g_part[c][i1]; }

    float m = fmaxf(l0, l1);
#pragma unroll
    for (int off = 16; off; off >>= 1) m = fmaxf(m, __shfl_xor_sync(0xFFFFFFFFu, m, off));
    if ((t & 31) == 0) red[t >> 5] = m;
    __syncthreads();
    if (t < 32) {
        float x = red[t];
#pragma unroll
        for (int off = 16; off; off >>= 1) x = fmaxf(x, __shfl_xor_sync(0xFFFFFFFFu, x, off));
        if (t == 0) red[0] = x;
    }
    __syncthreads();
    const float M = red[0];
    __syncthreads();

    float e0 = expf(l0 - M), e1 = expf(l1 - M);
    float s = e0 + e1;
#pragma unroll
    for (int off = 16; off; off >>= 1) s += __shfl_xor_sync(0xFFFFFFFFu, s, off);
    if ((t & 31) == 0) red[t >> 5] = s;
    __syncthreads();
    if (t < 32) {
        float x = red[t];
#pragma unroll
        for (int off = 16; off; off >>= 1) x += __shfl_xor_sync(0xFFFFFFFFu, x, off);
        if (t == 0) red[0] = x;
    }
    __syncthreads();
    const float inv = 1.0f / red[0];
    out[i0] = e0 * inv;
    out[i1] = e1 * inv;
}

// ---------------- launch ----------------
extern "C" void kernel_launch(void* const* d_in, const int* in_sizes, int n_in,
                              void* d_out, int out_size) {
    const float* hid  = (const float*)d_in[0];   // [16,2048,1024]
    const float* enc  = (const float*)d_in[1];   // [16,2048,1024]
    const float* ct   = (const float*)d_in[2];   // [16,1024]
    const float* W    = (const float*)d_in[3];   // [1024,3072]
    const float* bias = (const float*)d_in[4];   // [1024]
    const float* v    = (const float*)d_in[5];   // [1024]
    float* out = (float*)d_out;                  // [16,2048]

    cudaFuncSetAttribute(k_gemm, cudaFuncAttributeMaxDynamicSharedMemorySize, SMEM_TOTAL);

    k_convA<<<(unsigned)((size_t)Mtot * Dn / 4 / 256), 256>>>(hid, enc);
    k_convB<<<(unsigned)((size_t)On * Ktot / 4 / 256), 256>>>(W);
    k_cb<<<Bn * On / 8, 256>>>(ct, W, bias);
    dim3 grid(NCH, MT);
    k_gemm<<<grid, THREADS, SMEM_TOTAL>>>(v);
    k_softmax<<<Bn, 1024>>>(out);
}

// round 14
// speedup vs baseline: 1.6060x; 1.1332x over previous
#include <cuda_runtime.h>
#include <cuda_bf16.h>
#include <cstdint>
#include <cstddef>

#define DINL __device__ __forceinline__

// ---------------- problem constants ----------------
namespace {
constexpr int Bn = 16, Sn = 2048, Dn = 1024, On = 1024;
constexpr int Mtot = Bn * Sn;           // 32768 rows
constexpr int Ktot = 2 * Dn;            // 2048 (hidden | enc concat)
constexpr int M_TILE = 128, N_TILE = 128, K_TILE = 32;
constexpr int KT  = Ktot / K_TILE;      // 64 k-iterations
constexpr int NCH = On / N_TILE;        // 8 n-chunks
constexpr int MT  = Mtot / M_TILE;      // 256 m-tiles
constexpr int THREADS = 128;            // 4 warps: 2 (M) x 2 (N), warp tile 64x64

// smem: padded rows -> conflict-free ldmatrix & cp.async stores
constexpr int ROW_PAD = 40;                         // halves per 32-half row (80 B)
constexpr int ARR = 128 * ROW_PAD * 2;              // 10240 B per operand array
constexpr int A_HI = 0, A_LO = ARR, B_HI = 2 * ARR, B_LO = 3 * ARR;
constexpr int STAGE_BYTES = 4 * ARR;                // 40960 B
constexpr int STAGES = 2;
constexpr int SMEM_TOTAL = STAGES * STAGE_BYTES;    // 81920 B -> 2 CTAs/SM
constexpr int CHUNKS = 2048;                        // 16B chunks per stage
}

// ---------------- scratch (device globals; no allocs allowed) ----------------
__device__ __nv_bfloat16 g_Ahi[(size_t)Mtot * Ktot];   // 128 MB
__device__ __nv_bfloat16 g_Alo[(size_t)Mtot * Ktot];   // 128 MB
__device__ __nv_bfloat16 g_Bhi[(size_t)On * Ktot];     // 4 MB
__device__ __nv_bfloat16 g_Blo[(size_t)On * Ktot];     // 4 MB
__device__ float g_cb[Bn * On];                        // c_t @ W2^T + bias
__device__ float g_part[NCH][Mtot];                    // per-n-chunk logit partials

// ---------------- PTX helpers (base sm_80+ only; no tcgen05 on sm_103 base) ----
DINL uint32_t smem_u32(const void* p) {
    uint32_t a;
    asm("{ .reg .u64 t; cvta.to.shared.u64 t, %1; cvt.u32.u64 %0, t; }" : "=r"(a) : "l"(p));
    return a;
}
DINL void cp_async16(uint32_t s, const void* g) {
    asm volatile("cp.async.cg.shared.global [%0], [%1], 16;" :: "r"(s), "l"(g));
}
DINL void cp_commit() { asm volatile("cp.async.commit_group;" ::: "memory"); }
template <int N> DINL void cp_wait() { asm volatile("cp.async.wait_group %0;" :: "n"(N) : "memory"); }

DINL void ldsm_x4(uint32_t* r, uint32_t addr) {
    asm volatile("ldmatrix.sync.aligned.m8n8.x4.shared.b16 {%0,%1,%2,%3}, [%4];"
                 : "=r"(r[0]), "=r"(r[1]), "=r"(r[2]), "=r"(r[3]) : "r"(addr));
}
DINL void mma_bf16(float* c, const uint32_t* a, const uint32_t* b) {
    asm volatile(
        "mma.sync.aligned.m16n8k16.row.col.f32.bf16.bf16.f32 "
        "{%0,%1,%2,%3}, {%4,%5,%6,%7}, {%8,%9}, {%0,%1,%2,%3};"
        : "+f"(c[0]), "+f"(c[1]), "+f"(c[2]), "+f"(c[3])
        : "r"(a[0]), "r"(a[1]), "r"(a[2]), "r"(a[3]), "r"(b[0]), "r"(b[1]));
}

// ---------------- fp32 -> bf16 hi/lo split ----------------
DINL void split_store(float4 x, __nv_bfloat16* hi, __nv_bfloat16* lo) {
    float xs[4] = {x.x, x.y, x.z, x.w};
    __nv_bfloat16 h[4], l[4];
#pragma unroll
    for (int i = 0; i < 4; ++i) {
        h[i] = __float2bfloat16(xs[i]);
        l[i] = __float2bfloat16(xs[i] - __bfloat162float(h[i]));
    }
    *reinterpret_cast<uint2*>(hi) = *reinterpret_cast<const uint2*>(h);
    *reinterpret_cast<uint2*>(lo) = *reinterpret_cast<const uint2*>(l);
}

// A = [hidden | enc] as [Mtot x Ktot] hi/lo bf16
__global__ void __launch_bounds__(256) k_convA(const float* __restrict__ hid,
                                               const float* __restrict__ enc) {
    size_t i = (size_t)blockIdx.x * blockDim.x + threadIdx.x;
    constexpr size_t TOT = (size_t)Mtot * Dn / 4;
    if (i >= TOT) return;
    size_t row = (i * 4) / Dn;
    size_t col = (i * 4) % Dn;
    float4 h = reinterpret_cast<const float4*>(hid)[i];
    float4 e = reinterpret_cast<const float4*>(enc)[i];
    size_t o = row * Ktot + col;
    split_store(h, g_Ahi + o, g_Alo + o);
    split_store(e, g_Ahi + o + Dn, g_Alo + o + Dn);
}

// Bcat[o][k] = k<1024 ? W[o][k] : W[o][2048 + (k-1024)]
__global__ void __launch_bounds__(256) k_convB(const float* __restrict__ W) {
    size_t i = (size_t)blockIdx.x * blockDim.x + threadIdx.x;
    constexpr size_t TOT = (size_t)On * Ktot / 4;
    if (i >= TOT) return;
    size_t o = (i * 4) / Ktot;
    size_t k = (i * 4) % Ktot;
    size_t src = o * (size_t)(3 * Dn) + (k < (size_t)Dn ? k : k + Dn);
    float4 w = *reinterpret_cast<const float4*>(W + src);
    split_store(w, g_Bhi + o * Ktot + k, g_Blo + o * Ktot + k);
}

// cb[b][o] = c_t[b] . W[o][1024:2048] + bias[o]   (one warp per output, fp32 exact)
__global__ void __launch_bounds__(256) k_cb(const float* __restrict__ ct,
                                            const float* __restrict__ W,
                                            const float* __restrict__ bias) {
    int gw = blockIdx.x * 8 + (threadIdx.x >> 5);
    int lane = threadIdx.x & 31;
    int b = gw >> 10;
    int o = gw & 1023;
    const float* c = ct + (size_t)b * Dn;
    const float* w = W + (size_t)o * (3 * Dn) + Dn;
    float s = 0.f;
    for (int k = lane; k < Dn; k += 32) s += c[k] * w[k];
#pragma unroll
    for (int off = 16; off; off >>= 1) s += __shfl_xor_sync(0xFFFFFFFFu, s, off);
    if (lane == 0) g_cb[b * On + o] = s + bias[o];
}

// ---------------- fused split-bf16 GEMM (mma.sync) + relu + dot(v) ----------------
// one 16B chunk of a stage: cid in [0, 2048)
DINL void load_chunk(uint32_t stg, const __nv_bfloat16* Ah, const __nv_bfloat16* Al,
                     const __nv_bfloat16* Bh, const __nv_bfloat16* Bl, int kb, int cid) {
    const int arr = cid >> 9;                 // 0:Ahi 1:Alo 2:Bhi 3:Blo
    const int c = cid & 511;
    const int row = c & 127, kc = c >> 7;     // kc in 0..3
    const uint32_t so = (uint32_t)(arr * ARR + row * (ROW_PAD * 2) + kc * 16);
    const size_t go = (size_t)row * Ktot + kb + kc * 8;
    const __nv_bfloat16* src = (arr == 0) ? Ah : (arr == 1) ? Al : (arr == 2) ? Bh : Bl;
    cp_async16(stg + so, src + go);
}

__global__ void __launch_bounds__(THREADS, 2) k_gemm(const float* __restrict__ v) {
    extern __shared__ char smem[];
    const uint32_t sb = smem_u32(smem);
    const int tid  = threadIdx.x;
    const int lane = tid & 31, wid = tid >> 5;
    const int wm = wid >> 1, wn = wid & 1;        // 2 x 2 warp grid, warp tile 64x64
    const int nch = blockIdx.x;                   // fast-varying: 8 CTAs share A via L2
    const int m_base = blockIdx.y * M_TILE;
    const int n_base = nch * N_TILE;
    const int bidx = m_base / Sn;                 // tile sits in one batch (128 | 2048)

    const __nv_bfloat16* Ah = g_Ahi + (size_t)m_base * Ktot;
    const __nv_bfloat16* Al = g_Alo + (size_t)m_base * Ktot;
    const __nv_bfloat16* Bh = g_Bhi + (size_t)n_base * Ktot;
    const __nv_bfloat16* Bl = g_Blo + (size_t)n_base * Ktot;

    // ldmatrix per-lane smem offsets (bytes within a stage array)
    const int r_in = lane & 7, grp = lane >> 3;
    uint32_t a_off[4], b_off[4];
#pragma unroll
    for (int mt = 0; mt < 4; ++mt) {
        int row = wm * 64 + mt * 16 + r_in + (grp & 1) * 8;   // groups 0/2: rows, 1/3: rows+8
        a_off[mt] = (uint32_t)(row * (ROW_PAD * 2) + ((grp >> 1) * 8) * 2);  // grp 2,3: k+8
    }
#pragma unroll
    for (int i = 0; i < 4; ++i) {
        int row = wn * 64 + i * 16 + r_in + (grp >> 1) * 8;   // groups 0/1: n, 2/3: n+8
        b_off[i] = (uint32_t)(row * (ROW_PAD * 2) + ((grp & 1) * 8) * 2);    // grp 1,3: k+8
    }

    float acc[4][8][4];                           // [mt][n8-frag][quad]
#pragma unroll
    for (int a = 0; a < 4; ++a)
#pragma unroll
        for (int b = 0; b < 8; ++b)
#pragma unroll
            for (int c = 0; c < 4; ++c) acc[a][b][c] = 0.f;

    // prologue: fill stage 0  (2048 chunks / 128 threads = 16 per thread)
#pragma unroll
    for (int j = 0; j < CHUNKS / THREADS; ++j)
        load_chunk(sb, Ah, Al, Bh, Bl, 0, j * THREADS + tid);
    cp_commit();

#pragma unroll 1
    for (int kt = 0; kt < KT; ++kt) {
        cp_wait<0>();
        __syncthreads();
        const uint32_t stg  = sb + (uint32_t)(kt & 1) * STAGE_BYTES;
        const uint32_t nstg = sb + (uint32_t)((kt + 1) & 1) * STAGE_BYTES;
        const bool pf = (kt + 1 < KT);
        const int nkb = (kt + 1) * K_TILE;
#pragma unroll
        for (int k16 = 0; k16 < 2; ++k16) {
            // B fragments for this k16 (4 n16-frags x hi/lo)
            uint32_t bh[4][4], bl[4][4];
#pragma unroll
            for (int i = 0; i < 4; ++i) {
                ldsm_x4(bh[i], stg + B_HI + b_off[i] + k16 * 32);
                ldsm_x4(bl[i], stg + B_LO + b_off[i] + k16 * 32);
            }
            // software-pipelined A fragments
            uint32_t ah[2][4], al[2][4];
            ldsm_x4(ah[0], stg + A_HI + a_off[0] + k16 * 32);
            ldsm_x4(al[0], stg + A_LO + a_off[0] + k16 * 32);
#pragma unroll
            for (int mt = 0; mt < 4; ++mt) {
                const int cur = mt & 1, nxt = cur ^ 1;
                if (mt < 3) {
                    ldsm_x4(ah[nxt], stg + A_HI + a_off[mt + 1] + k16 * 32);
                    ldsm_x4(al[nxt], stg + A_LO + a_off[mt + 1] + k16 * 32);
                }
                // spread next-stage prefetch: 2 chunks/thread per inner it (8 its)
                const int it = k16 * 4 + mt;
                if (pf) {
                    load_chunk(nstg, Ah, Al, Bh, Bl, nkb, (2 * it) * THREADS + tid);
                    load_chunk(nstg, Ah, Al, Bh, Bl, nkb, (2 * it + 1) * THREADS + tid);
                }
#pragma unroll
                for (int nt = 0; nt < 8; ++nt) {
                    const uint32_t* bhf = &bh[nt >> 1][(nt & 1) * 2];
                    const uint32_t* blf = &bl[nt >> 1][(nt & 1) * 2];
                    mma_bf16(acc[mt][nt], ah[cur], bhf);   // hi*hi
                    mma_bf16(acc[mt][nt], ah[cur], blf);   // hi*lo
                    mma_bf16(acc[mt][nt], al[cur], bhf);   // lo*hi
                }
            }
        }
        cp_commit();
    }

    // ---- fused epilogue: partial[row] = sum_n relu(acc + cb[n]) * v[n] ----
    __syncthreads();                               // stages dead; reuse smem
    float* red = reinterpret_cast<float*>(smem);   // [128 rows][2 wn]
    const float* cbp = g_cb + bidx * On + n_base;
    const float* vp  = v + n_base;
    float cbv[8][2], vv[8][2];
#pragma unroll
    for (int nt = 0; nt < 8; ++nt)
#pragma unroll
        for (int j = 0; j < 2; ++j) {
            int n = wn * 64 + nt * 8 + 2 * (lane & 3) + j;
            cbv[nt][j] = cbp[n];
            vv[nt][j]  = vp[n];
        }
#pragma unroll
    for (int mt = 0; mt < 4; ++mt)
#pragma unroll
        for (int h = 0; h < 2; ++h) {
            float s = 0.f;
#pragma unroll
            for (int nt = 0; nt < 8; ++nt)
#pragma unroll
                for (int j = 0; j < 2; ++j) {
                    float e = acc[mt][nt][2 * h + j] + cbv[nt][j];
                    s += fmaxf(e, 0.f) * vv[nt][j];
                }
            s += __shfl_xor_sync(0xFFFFFFFFu, s, 1);
            s += __shfl_xor_sync(0xFFFFFFFFu, s, 2);
            if ((lane & 3) == 0) {
                int row = wm * 64 + mt * 16 + (lane >> 2) + 8 * h;
                red[row * 2 + wn] = s;
            }
        }
    __syncthreads();
    if (tid < M_TILE) {
        g_part[nch][m_base + tid] = red[tid * 2] + red[tid * 2 + 1];
    }
}

// ---------------- softmax over S per batch ----------------
__global__ void __launch_bounds__(1024) k_softmax(float* __restrict__ out) {
    __shared__ float red[32];
    const int b = blockIdx.x;
    const int t = threadIdx.x;
    const int i0 = b * Sn + t;
    const int i1 = i0 + 1024;
    float l0 = 0.f, l1 = 0.f;
#pragma unroll
    for (int c = 0; c < NCH; ++c) { l0 += g_part[c][i0]; l1 += g_part[c][i1]; }

    float m = fmaxf(l0, l1);
#pragma unroll
    for (int off = 16; off; off >>= 1) m = fmaxf(m, __shfl_xor_sync(0xFFFFFFFFu, m, off));
    if ((t & 31) == 0) red[t >> 5] = m;
    __syncthreads();
    if (t < 32) {
        float x = red[t];
#pragma unroll
        for (int off = 16; off; off >>= 1) x = fmaxf(x, __shfl_xor_sync(0xFFFFFFFFu, x, off));
        if (t == 0) red[0] = x;
    }
    __syncthreads();
    const float M = red[0];
    __syncthreads();

    float e0 = expf(l0 - M), e1 = expf(l1 - M);
    float s = e0 + e1;
#pragma unroll
    for (int off = 16; off; off >>= 1) s += __shfl_xor_sync(0xFFFFFFFFu, s, off);
    if ((t & 31) == 0) red[t >> 5] = s;
    __syncthreads();
    if (t < 32) {
        float x = red[t];
#pragma unroll
        for (int off = 16; off; off >>= 1) x += __shfl_xor_sync(0xFFFFFFFFu, x, off);
        if (t == 0) red[0] = x;
    }
    __syncthreads();
    const float inv = 1.0f / red[0];
    out[i0] = e0 * inv;
    out[i1] = e1 * inv;
}

// ---------------- launch ----------------
extern "C" void kernel_launch(void* const* d_in, const int* in_sizes, int n_in,
                              void* d_out, int out_size) {
    const float* hid  = (const float*)d_in[0];   // [16,2048,1024]
    const float* enc  = (const float*)d_in[1];   // [16,2048,1024]
    const float* ct   = (const float*)d_in[2];   // [16,1024]
    const float* W    = (const float*)d_in[3];   // [1024,3072]
    const float* bias = (const float*)d_in[4];   // [1024]
    const float* v    = (const float*)d_in[5];   // [1024]
    float* out = (float*)d_out;                  // [16,2048]

    cudaFuncSetAttribute(k_gemm, cudaFuncAttributeMaxDynamicSharedMemorySize, SMEM_TOTAL);

    k_convA<<<(unsigned)((size_t)Mtot * Dn / 4 / 256), 256>>>(hid, enc);
    k_convB<<<(unsigned)((size_t)On * Ktot / 4 / 256), 256>>>(W);
    k_cb<<<Bn * On / 8, 256>>>(ct, W, bias);
    dim3 grid(NCH, MT);
    k_gemm<<<grid, THREADS, SMEM_TOTAL>>>(v);
    k_softmax<<<Bn, 1024>>>(out);
}

// round 15
// speedup vs baseline: 1.6627x; 1.0353x over previous
#include <cuda_runtime.h>
#include <cuda_bf16.h>
#include <cstdint>
#include <cstddef>

#define DINL __device__ __forceinline__

// ---------------- problem constants ----------------
namespace {
constexpr int Bn = 16, Sn = 2048, Dn = 1024, On = 1024;
constexpr int Mtot = Bn * Sn;           // 32768 rows
constexpr int Ktot = 2 * Dn;            // 2048 (hidden | enc concat)
constexpr int M_TILE = 128, N_TILE = 256, K_TILE = 32;
constexpr int KT  = Ktot / K_TILE;      // 64 k-iterations
constexpr int NCH = On / N_TILE;        // 4 n-chunks
constexpr int MT  = Mtot / M_TILE;      // 256 m-tiles
constexpr int THREADS = 256;            // 8 warps: 2 (M) x 4 (N), warp tile 64x64

// smem: padded rows (80 B pitch for 64B k-rows) -> conflict-free ldsm/cp.async
constexpr int ROW_PITCH = 80;                       // bytes per 32-half row
constexpr int ARR_A = 128 * ROW_PITCH;              // 10240 B per A operand array
constexpr int ARR_B = 256 * ROW_PITCH;              // 20480 B per B operand array
constexpr int A_HI = 0, A_LO = ARR_A;               // A arrays
constexpr int B_HI = 2 * ARR_A;                     // 20480
constexpr int B_LO = 2 * ARR_A + ARR_B;             // 40960
constexpr int STAGE_BYTES = 2 * ARR_A + 2 * ARR_B;  // 61440 B
constexpr int STAGES = 2;
constexpr int SMEM_TOTAL = STAGES * STAGE_BYTES;    // 122880 B (1 CTA/SM)
constexpr int CHUNKS = 3072;                        // 16B chunks per stage
}

// ---------------- scratch (device globals; no allocs allowed) ----------------
__device__ __nv_bfloat16 g_Ahi[(size_t)Mtot * Ktot];   // 128 MB
__device__ __nv_bfloat16 g_Alo[(size_t)Mtot * Ktot];   // 128 MB
__device__ __nv_bfloat16 g_Bhi[(size_t)On * Ktot];     // 4 MB
__device__ __nv_bfloat16 g_Blo[(size_t)On * Ktot];     // 4 MB
__device__ float g_cb[Bn * On];                        // c_t @ W2^T + bias
__device__ float g_part[NCH][Mtot];                    // per-n-chunk logit partials

// ---------------- PTX helpers (base sm_80+ only; no tcgen05 on sm_103 base) ----
DINL uint32_t smem_u32(const void* p) {
    uint32_t a;
    asm("{ .reg .u64 t; cvta.to.shared.u64 t, %1; cvt.u32.u64 %0, t; }" : "=r"(a) : "l"(p));
    return a;
}
DINL void cp_async16(uint32_t s, const void* g) {
    asm volatile("cp.async.cg.shared.global [%0], [%1], 16;" :: "r"(s), "l"(g));
}
DINL void cp_commit() { asm volatile("cp.async.commit_group;" ::: "memory"); }
template <int N> DINL void cp_wait() { asm volatile("cp.async.wait_group %0;" :: "n"(N) : "memory"); }

DINL void ldsm_x4(uint32_t* r, uint32_t addr) {
    asm volatile("ldmatrix.sync.aligned.m8n8.x4.shared.b16 {%0,%1,%2,%3}, [%4];"
                 : "=r"(r[0]), "=r"(r[1]), "=r"(r[2]), "=r"(r[3]) : "r"(addr));
}
DINL void mma_bf16(float* c, const uint32_t* a, const uint32_t* b) {
    asm volatile(
        "mma.sync.aligned.m16n8k16.row.col.f32.bf16.bf16.f32 "
        "{%0,%1,%2,%3}, {%4,%5,%6,%7}, {%8,%9}, {%0,%1,%2,%3};"
        : "+f"(c[0]), "+f"(c[1]), "+f"(c[2]), "+f"(c[3])
        : "r"(a[0]), "r"(a[1]), "r"(a[2]), "r"(a[3]), "r"(b[0]), "r"(b[1]));
}

// ---------------- fp32 -> bf16 hi/lo split ----------------
DINL void split_store(float4 x, __nv_bfloat16* hi, __nv_bfloat16* lo) {
    float xs[4] = {x.x, x.y, x.z, x.w};
    __nv_bfloat16 h[4], l[4];
#pragma unroll
    for (int i = 0; i < 4; ++i) {
        h[i] = __float2bfloat16(xs[i]);
        l[i] = __float2bfloat16(xs[i] - __bfloat162float(h[i]));
    }
    *reinterpret_cast<uint2*>(hi) = *reinterpret_cast<const uint2*>(h);
    *reinterpret_cast<uint2*>(lo) = *reinterpret_cast<const uint2*>(l);
}

// A = [hidden | enc] as [Mtot x Ktot] hi/lo bf16
__global__ void __launch_bounds__(256) k_convA(const float* __restrict__ hid,
                                               const float* __restrict__ enc) {
    size_t i = (size_t)blockIdx.x * blockDim.x + threadIdx.x;
    constexpr size_t TOT = (size_t)Mtot * Dn / 4;
    if (i >= TOT) return;
    size_t row = (i * 4) / Dn;
    size_t col = (i * 4) % Dn;
    float4 h = reinterpret_cast<const float4*>(hid)[i];
    float4 e = reinterpret_cast<const float4*>(enc)[i];
    size_t o = row * Ktot + col;
    split_store(h, g_Ahi + o, g_Alo + o);
    split_store(e, g_Ahi + o + Dn, g_Alo + o + Dn);
}

// Bcat[o][k] = k<1024 ? W[o][k] : W[o][2048 + (k-1024)]
__global__ void __launch_bounds__(256) k_convB(const float* __restrict__ W) {
    size_t i = (size_t)blockIdx.x * blockDim.x + threadIdx.x;
    constexpr size_t TOT = (size_t)On * Ktot / 4;
    if (i >= TOT) return;
    size_t o = (i * 4) / Ktot;
    size_t k = (i * 4) % Ktot;
    size_t src = o * (size_t)(3 * Dn) + (k < (size_t)Dn ? k : k + Dn);
    float4 w = *reinterpret_cast<const float4*>(W + src);
    split_store(w, g_Bhi + o * Ktot + k, g_Blo + o * Ktot + k);
}

// cb[b][o] = c_t[b] . W[o][1024:2048] + bias[o]   (one warp per output, fp32 exact)
__global__ void __launch_bounds__(256) k_cb(const float* __restrict__ ct,
                                            const float* __restrict__ W,
                                            const float* __restrict__ bias) {
    int gw = blockIdx.x * 8 + (threadIdx.x >> 5);
    int lane = threadIdx.x & 31;
    int b = gw >> 10;
    int o = gw & 1023;
    const float* c = ct + (size_t)b * Dn;
    const float* w = W + (size_t)o * (3 * Dn) + Dn;
    float s = 0.f;
    for (int k = lane; k < Dn; k += 32) s += c[k] * w[k];
#pragma unroll
    for (int off = 16; off; off >>= 1) s += __shfl_xor_sync(0xFFFFFFFFu, s, off);
    if (lane == 0) g_cb[b * On + o] = s + bias[o];
}

// ---------------- fused split-bf16 GEMM (mma.sync) + relu + dot(v) ----------------
// one 16B chunk of a stage: cid in [0, 3072)
// A: cid [0,1024) -> Ahi/Alo (512 each, 128 rows x 4 kc)
// B: cid [1024,3072) -> Bhi/Blo (1024 each, 256 rows x 4 kc)
DINL void load_chunk(uint32_t stg, const __nv_bfloat16* Ah, const __nv_bfloat16* Al,
                     const __nv_bfloat16* Bh, const __nv_bfloat16* Bl, int kb, int cid) {
    int row, kc;
    uint32_t so;
    const __nv_bfloat16* src;
    if (cid < 1024) {
        const int arr = cid >> 9;             // 0:Ahi 1:Alo
        const int c = cid & 511;
        row = c & 127; kc = c >> 7;
        so = (uint32_t)(arr * ARR_A + row * ROW_PITCH + kc * 16);
        src = arr ? Al : Ah;
    } else {
        const int c2 = cid - 1024;
        const int arr = c2 >> 10;             // 0:Bhi 1:Blo
        const int c = c2 & 1023;
        row = c & 255; kc = c >> 8;
        so = (uint32_t)(B_HI + arr * ARR_B + row * ROW_PITCH + kc * 16);
        src = arr ? Bl : Bh;
    }
    const size_t go = (size_t)row * Ktot + kb + kc * 8;
    cp_async16(stg + so, src + go);
}

__global__ void __launch_bounds__(THREADS, 1) k_gemm(const float* __restrict__ v) {
    extern __shared__ char smem[];
    const uint32_t sb = smem_u32(smem);
    const int tid  = threadIdx.x;
    const int lane = tid & 31, wid = tid >> 5;
    const int wm = wid >> 2, wn = wid & 3;        // 2 x 4 warp grid, warp tile 64x64
    const int nch = blockIdx.x;                   // fast-varying: 4 CTAs share A via L2
    const int m_base = blockIdx.y * M_TILE;
    const int n_base = nch * N_TILE;
    const int bidx = m_base / Sn;                 // tile sits in one batch (128 | 2048)

    const __nv_bfloat16* Ah = g_Ahi + (size_t)m_base * Ktot;
    const __nv_bfloat16* Al = g_Alo + (size_t)m_base * Ktot;
    const __nv_bfloat16* Bh = g_Bhi + (size_t)n_base * Ktot;
    const __nv_bfloat16* Bl = g_Blo + (size_t)n_base * Ktot;

    // ldmatrix per-lane smem offsets (bytes within a stage)
    const int r_in = lane & 7, grp = lane >> 3;
    uint32_t a_off[4], b_off[4];
#pragma unroll
    for (int mt = 0; mt < 4; ++mt) {
        int row = wm * 64 + mt * 16 + r_in + (grp & 1) * 8;   // groups 0/2: rows, 1/3: rows+8
        a_off[mt] = (uint32_t)(row * ROW_PITCH + ((grp >> 1) * 8) * 2);  // grp 2,3: k+8
    }
#pragma unroll
    for (int i = 0; i < 4; ++i) {
        int row = wn * 64 + i * 16 + r_in + (grp >> 1) * 8;   // groups 0/1: n, 2/3: n+8
        b_off[i] = (uint32_t)(row * ROW_PITCH + ((grp & 1) * 8) * 2);    // grp 1,3: k+8
    }

    float acc[4][8][4];                           // [mt][n8-frag][quad]
#pragma unroll
    for (int a = 0; a < 4; ++a)
#pragma unroll
        for (int b = 0; b < 8; ++b)
#pragma unroll
            for (int c = 0; c < 4; ++c) acc[a][b][c] = 0.f;

    // prologue: fill stage 0  (3072 chunks / 256 threads = 12 per thread)
#pragma unroll
    for (int j = 0; j < CHUNKS / THREADS; ++j)
        load_chunk(sb, Ah, Al, Bh, Bl, 0, j * THREADS + tid);
    cp_commit();

#pragma unroll 1
    for (int kt = 0; kt < KT; ++kt) {
        cp_wait<0>();
        __syncthreads();
        const uint32_t stg  = sb + (uint32_t)(kt & 1) * STAGE_BYTES;
        const uint32_t nstg = sb + (uint32_t)((kt + 1) & 1) * STAGE_BYTES;
        const bool pf = (kt + 1 < KT);
        const int nkb = (kt + 1) * K_TILE;
#pragma unroll
        for (int k16 = 0; k16 < 2; ++k16) {
            // B fragments for this k16 (4 n16-frags x hi/lo)
            uint32_t bh[4][4], bl[4][4];
#pragma unroll
            for (int i = 0; i < 4; ++i) {
                ldsm_x4(bh[i], stg + B_HI + b_off[i] + k16 * 32);
                ldsm_x4(bl[i], stg + B_LO + b_off[i] + k16 * 32);
            }
            // software-pipelined A fragments
            uint32_t ah[2][4], al[2][4];
            ldsm_x4(ah[0], stg + A_HI + a_off[0] + k16 * 32);
            ldsm_x4(al[0], stg + A_LO + a_off[0] + k16 * 32);
#pragma unroll
            for (int mt = 0; mt < 4; ++mt) {
                const int cur = mt & 1, nxt = cur ^ 1;
                if (mt < 3) {
                    ldsm_x4(ah[nxt], stg + A_HI + a_off[mt + 1] + k16 * 32);
                    ldsm_x4(al[nxt], stg + A_LO + a_off[mt + 1] + k16 * 32);
                }
                // spread next-stage prefetch: 12 chunks/thread over 8 inner its
                const int it = k16 * 4 + mt;               // 0..7
                if (pf) {
                    if (it < 4) {
                        load_chunk(nstg, Ah, Al, Bh, Bl, nkb, (2 * it) * THREADS + tid);
                        load_chunk(nstg, Ah, Al, Bh, Bl, nkb, (2 * it + 1) * THREADS + tid);
                    } else {
                        load_chunk(nstg, Ah, Al, Bh, Bl, nkb, (4 + it) * THREADS + tid);
                    }
                }
#pragma unroll
                for (int nt = 0; nt < 8; ++nt) {
                    const uint32_t* bhf = &bh[nt >> 1][(nt & 1) * 2];
                    const uint32_t* blf = &bl[nt >> 1][(nt & 1) * 2];
                    mma_bf16(acc[mt][nt], ah[cur], bhf);   // hi*hi
                    mma_bf16(acc[mt][nt], ah[cur], blf);   // hi*lo
                    mma_bf16(acc[mt][nt], al[cur], bhf);   // lo*hi
                }
            }
        }
        cp_commit();
    }

    // ---- fused epilogue: partial[row] = sum_n relu(acc + cb[n]) * v[n] ----
    __syncthreads();                               // stages dead; reuse smem
    float* red = reinterpret_cast<float*>(smem);   // [128 rows][4 wn]
    const float* cbp = g_cb + bidx * On + n_base;
    const float* vp  = v + n_base;
    float cbv[8][2], vv[8][2];
#pragma unroll
    for (int nt = 0; nt < 8; ++nt)
#pragma unroll
        for (int j = 0; j < 2; ++j) {
            int n = wn * 64 + nt * 8 + 2 * (lane & 3) + j;
            cbv[nt][j] = cbp[n];
            vv[nt][j]  = vp[n];
        }
#pragma unroll
    for (int mt = 0; mt < 4; ++mt)
#pragma unroll
        for (int h = 0; h < 2; ++h) {
            float s = 0.f;
#pragma unroll
            for (int nt = 0; nt < 8; ++nt)
#pragma unroll
                for (int j = 0; j < 2; ++j) {
                    float e = acc[mt][nt][2 * h + j] + cbv[nt][j];
                    s += fmaxf(e, 0.f) * vv[nt][j];
                }
            s += __shfl_xor_sync(0xFFFFFFFFu, s, 1);
            s += __shfl_xor_sync(0xFFFFFFFFu, s, 2);
            if ((lane & 3) == 0) {
                int row = wm * 64 + mt * 16 + (lane >> 2) + 8 * h;
                red[row * 4 + wn] = s;
            }
        }
    __syncthreads();
    if (tid < M_TILE) {
        g_part[nch][m_base + tid] =
            red[tid * 4] + red[tid * 4 + 1] + red[tid * 4 + 2] + red[tid * 4 + 3];
    }
}

// ---------------- softmax over S per batch ----------------
__global__ void __launch_bounds__(1024) k_softmax(float* __restrict__ out) {
    __shared__ float red[32];
    const int b = blockIdx.x;
    const int t = threadIdx.x;
    const int i0 = b * Sn + t;
    const int i1 = i0 + 1024;
    float l0 = 0.f, l1 = 0.f;
#pragma unroll
    for (int c = 0; c < NCH; ++c) { l0 += g_part[c][i0]; l1 += g_part[c][i1]; }

    float m = fmaxf(l0, l1);
#pragma unroll
    for (int off = 16; off; off >>= 1) m = fmaxf(m, __shfl_xor_sync(0xFFFFFFFFu, m, off));
    if ((t & 31) == 0) red[t >> 5] = m;
    __syncthreads();
    if (t < 32) {
        float x = red[t];
#pragma unroll
        for (int off = 16; off; off >>= 1) x = fmaxf(x, __shfl_xor_sync(0xFFFFFFFFu, x, off));
        if (t == 0) red[0] = x;
    }
    __syncthreads();
    const float M = red[0];
    __syncthreads();

    float e0 = expf(l0 - M), e1 = expf(l1 - M);
    float s = e0 + e1;
#pragma unroll
    for (int off = 16; off; off >>= 1) s += __shfl_xor_sync(0xFFFFFFFFu, s, off);
    if ((t & 31) == 0) red[t >> 5] = s;
    __syncthreads();
    if (t < 32) {
        float x = red[t];
#pragma unroll
        for (int off = 16; off; off >>= 1) x += __shfl_xor_sync(0xFFFFFFFFu, x, off);
        if (t == 0) red[0] = x;
    }
    __syncthreads();
    const float inv = 1.0f / red[0];
    out[i0] = e0 * inv;
    out[i1] = e1 * inv;
}

// ---------------- launch ----------------
extern "C" void kernel_launch(void* const* d_in, const int* in_sizes, int n_in,
                              void* d_out, int out_size) {
    const float* hid  = (const float*)d_in[0];   // [16,2048,1024]
    const float* enc  = (const float*)d_in[1];   // [16,2048,1024]
    const float* ct   = (const float*)d_in[2];   // [16,1024]
    const float* W    = (const float*)d_in[3];   // [1024,3072]
    const float* bias = (const float*)d_in[4];   // [1024]
    const float* v    = (const float*)d_in[5];   // [1024]
    float* out = (float*)d_out;                  // [16,2048]

    cudaFuncSetAttribute(k_gemm, cudaFuncAttributeMaxDynamicSharedMemorySize, SMEM_TOTAL);

    k_convA<<<(unsigned)((size_t)Mtot * Dn / 4 / 256), 256>>>(hid, enc);
    k_convB<<<(unsigned)((size_t)On * Ktot / 4 / 256), 256>>>(W);
    k_cb<<<Bn * On / 8, 256>>>(ct, W, bias);
    dim3 grid(NCH, MT);
    k_gemm<<<grid, THREADS, SMEM_TOTAL>>>(v);
    k_softmax<<<Bn, 1024>>>(out);
}